// round 2
// baseline (speedup 1.0000x reference)
#include <cuda_runtime.h>
#include <math.h>
#include <stdint.h>

#define B_ 2
#define T_ 2048
#define C_ 1024
#define H_ 16
#define D_ 64

// Scratch (allocation-free rule: __device__ globals)
__device__ float g_q[B_*H_*T_*D_];   // (B,H,T,D)
__device__ float g_k[B_*H_*T_*D_];
__device__ float g_v[B_*H_*T_*D_];
__device__ float g_y[B_*T_*C_];      // attention output, (B,T,C)

// ---------------------------------------------------------------------------
// SGEMM: out[m,n] = sum_k A[m,k]*W[n,k] + bias[n]
// A: (4096,1024) row-major, W: (1024,1024) row-major (nn.Linear weight)
// MODE 0: scatter to (B,H,T,D) layout.  MODE 1: plain row-major (M,1024).
// 128x128x16 tiles, 256 threads, 8x8 per thread, strided column ownership.
// ---------------------------------------------------------------------------
template<int MODE>
__global__ __launch_bounds__(256, 2)
void sgemm_nt(const float* __restrict__ A, const float* __restrict__ W,
              const float* __restrict__ bias, float* __restrict__ out)
{
    __shared__ float As[16][129];
    __shared__ float Bs[16][129];

    const int tid = threadIdx.x;
    const int m0 = blockIdx.y * 128;
    const int n0 = blockIdx.x * 128;
    const int tr = tid >> 4;        // 0..15 : row group (8 rows each)
    const int tc = tid & 15;        // 0..15 : col lane (cols tc+16j)
    const int lr = tid >> 2;        // 0..63 : load row
    const int lc = (tid & 3) << 2;  // 0,4,8,12 : load k-col (float4)

    const float* Ap = A + (size_t)m0 * 1024;
    const float* Wp = W + (size_t)n0 * 1024;

    float acc[8][8];
#pragma unroll
    for (int i = 0; i < 8; i++)
#pragma unroll
        for (int j = 0; j < 8; j++) acc[i][j] = 0.f;

    for (int k0 = 0; k0 < 1024; k0 += 16) {
        float4 a0 = *(const float4*)(Ap + (size_t)lr       * 1024 + k0 + lc);
        float4 a1 = *(const float4*)(Ap + (size_t)(lr + 64) * 1024 + k0 + lc);
        float4 w0 = *(const float4*)(Wp + (size_t)lr       * 1024 + k0 + lc);
        float4 w1 = *(const float4*)(Wp + (size_t)(lr + 64) * 1024 + k0 + lc);
        __syncthreads();
        As[lc+0][lr] = a0.x; As[lc+1][lr] = a0.y; As[lc+2][lr] = a0.z; As[lc+3][lr] = a0.w;
        As[lc+0][lr+64] = a1.x; As[lc+1][lr+64] = a1.y; As[lc+2][lr+64] = a1.z; As[lc+3][lr+64] = a1.w;
        Bs[lc+0][lr] = w0.x; Bs[lc+1][lr] = w0.y; Bs[lc+2][lr] = w0.z; Bs[lc+3][lr] = w0.w;
        Bs[lc+0][lr+64] = w1.x; Bs[lc+1][lr+64] = w1.y; Bs[lc+2][lr+64] = w1.z; Bs[lc+3][lr+64] = w1.w;
        __syncthreads();
#pragma unroll
        for (int k = 0; k < 16; k++) {
            float ar[8], br[8];
#pragma unroll
            for (int i = 0; i < 8; i++) ar[i] = As[k][tr * 8 + i];
#pragma unroll
            for (int j = 0; j < 8; j++) br[j] = Bs[k][tc + 16 * j];
#pragma unroll
            for (int i = 0; i < 8; i++)
#pragma unroll
                for (int j = 0; j < 8; j++)
                    acc[i][j] = fmaf(ar[i], br[j], acc[i][j]);
        }
    }

#pragma unroll
    for (int i = 0; i < 8; i++) {
        const int m = m0 + tr * 8 + i;
#pragma unroll
        for (int j = 0; j < 8; j++) {
            const int n = n0 + tc + 16 * j;
            const float v = acc[i][j] + bias[n];
            if (MODE == 0) {
                const int b = m >> 11;      // m / T_
                const int t = m & (T_ - 1);
                const int h = n >> 6;       // n / D_
                const int d = n & (D_ - 1);
                out[(((size_t)b * H_ + h) * T_ + t) * D_ + d] = v;
            } else {
                out[(size_t)m * C_ + n] = v;
            }
        }
    }
}

// ---------------------------------------------------------------------------
// Causal/step mask computed analytically (matches reference construction):
// attend allowed iff  (q/32 == k/32)  ||  (k<=q && q%4!=3 && k%4!=3)
// masked = !allowed.
// ---------------------------------------------------------------------------
__device__ __forceinline__ bool causal_masked(int q, int k) {
    const bool step = (q >> 5) == (k >> 5);
    const bool tri  = (k <= q) && ((q & 3) != 3) && ((k & 3) != 3);
    return !(step || tri);
}

// ---------------------------------------------------------------------------
// Fused masked flash attention.
// Block: (b,h,qtile of 64 rows). Only visits K tiles k0 <= q0 (all later
// columns are provably masked: step chunks are 32 wide, 64-aligned, so
// nothing attends past its own 64-row tile's right edge).
// dynamic_mask read as uint32 words (nonzero == masked) -> correct for
// int32 {0,1} and float32 {0.0,1.0} encodings alike.
// ---------------------------------------------------------------------------
__global__ __launch_bounds__(256)
void attn_kernel(const uint32_t* __restrict__ dmask,   // (B,1,T,T), 4B elems
                 float* __restrict__ y)                // (B,T,C)
{
    extern __shared__ float sm[];
    float* Qs = sm;            // [64][64]
    float* Ks = Qs + 64 * 64;  // [64][65]  (odd stride: conflict-free reads)
    float* Vs = Ks + 64 * 65;  // [64][64]
    float* Ps = Vs + 64 * 64;  // [64][64]

    const int b  = blockIdx.z;
    const int h  = blockIdx.y;
    const int qi = (int)gridDim.x - 1 - (int)blockIdx.x;   // heavy tiles first
    const int q0 = qi * 64;

    const int tid = threadIdx.x;
    const int ty = tid >> 4;   // 0..15
    const int tx = tid & 15;   // 0..15

    const float* qg = g_q + (((size_t)b * H_ + h) * T_ + q0) * D_;
    const float* kg = g_k + (((size_t)b * H_ + h) * T_) * D_;
    const float* vg = g_v + (((size_t)b * H_ + h) * T_) * D_;

    // Load Q tile (64x64) with float4
#pragma unroll
    for (int i = 0; i < 4; i++) {
        const int lin = tid + i * 256;
        const int r = lin >> 4, c = (lin & 15) << 2;
        *(float4*)&Qs[r * 64 + c] = *(const float4*)&qg[(size_t)r * 64 + c];
    }

    float mi[4], li[4], acc[4][4];
#pragma unroll
    for (int i = 0; i < 4; i++) {
        mi[i] = -INFINITY; li[i] = 0.f;
#pragma unroll
        for (int j = 0; j < 4; j++) acc[i][j] = 0.f;
    }

    const int ntiles = qi + 1;
    for (int kt = 0; kt < ntiles; kt++) {
        const int k0 = kt * 64;
        // Load K (scalar into padded 65) and V (float4)
#pragma unroll
        for (int i = 0; i < 4; i++) {
            const int lin = tid + i * 256;
            const int r = lin >> 4, c = (lin & 15) << 2;
            float4 kv = *(const float4*)&kg[(size_t)(k0 + r) * 64 + c];
            Ks[r * 65 + c + 0] = kv.x;
            Ks[r * 65 + c + 1] = kv.y;
            Ks[r * 65 + c + 2] = kv.z;
            Ks[r * 65 + c + 3] = kv.w;
            *(float4*)&Vs[r * 64 + c] = *(const float4*)&vg[(size_t)(k0 + r) * 64 + c];
        }
        __syncthreads();

        // S = Q K^T (contraction over d)
        float s[4][4];
#pragma unroll
        for (int i = 0; i < 4; i++)
#pragma unroll
            for (int j = 0; j < 4; j++) s[i][j] = 0.f;
#pragma unroll
        for (int k = 0; k < 64; k++) {
            float qr[4], kr[4];
#pragma unroll
            for (int i = 0; i < 4; i++) qr[i] = Qs[(ty * 4 + i) * 64 + k];
#pragma unroll
            for (int j = 0; j < 4; j++) kr[j] = Ks[(tx + 16 * j) * 65 + k];
#pragma unroll
            for (int i = 0; i < 4; i++)
#pragma unroll
                for (int j = 0; j < 4; j++)
                    s[i][j] = fmaf(qr[i], kr[j], s[i][j]);
        }

        // scale + masks (dynamic from memory, causal computed)
        const uint32_t* dmp = dmask + ((size_t)b * T_ + q0) * T_ + k0;
#pragma unroll
        for (int i = 0; i < 4; i++) {
            const int r = ty * 4 + i;
            const int q = q0 + r;
#pragma unroll
            for (int j = 0; j < 4; j++) {
                const int c = tx + 16 * j;
                const int k = k0 + c;
                const bool mk = (dmp[(size_t)r * T_ + c] != 0u) || causal_masked(q, k);
                s[i][j] = mk ? -INFINITY : s[i][j] * 0.125f;
            }
        }

        // Online softmax (row-wise over 16 tx lanes within half-warp)
#pragma unroll
        for (int i = 0; i < 4; i++) {
            float mt = fmaxf(fmaxf(s[i][0], s[i][1]), fmaxf(s[i][2], s[i][3]));
            mt = fmaxf(mt, __shfl_xor_sync(0xffffffffu, mt, 8));
            mt = fmaxf(mt, __shfl_xor_sync(0xffffffffu, mt, 4));
            mt = fmaxf(mt, __shfl_xor_sync(0xffffffffu, mt, 2));
            mt = fmaxf(mt, __shfl_xor_sync(0xffffffffu, mt, 1));
            const float mnew = fmaxf(mi[i], mt);
            float alpha, rs = 0.f;
            if (mnew == -INFINITY) {
                // whole row masked so far: keep everything exactly zero
                alpha = 1.f;
#pragma unroll
                for (int j = 0; j < 4; j++) s[i][j] = 0.f;
            } else {
                alpha = __expf(mi[i] - mnew);  // mi=-inf -> 0
#pragma unroll
                for (int j = 0; j < 4; j++) {
                    s[i][j] = __expf(s[i][j] - mnew);  // s=-inf -> 0
                    rs += s[i][j];
                }
            }
            rs += __shfl_xor_sync(0xffffffffu, rs, 8);
            rs += __shfl_xor_sync(0xffffffffu, rs, 4);
            rs += __shfl_xor_sync(0xffffffffu, rs, 2);
            rs += __shfl_xor_sync(0xffffffffu, rs, 1);
            li[i] = li[i] * alpha + rs;
            mi[i] = mnew;
#pragma unroll
            for (int j = 0; j < 4; j++) acc[i][j] *= alpha;
            const int r = ty * 4 + i;
#pragma unroll
            for (int j = 0; j < 4; j++) Ps[r * 64 + tx + 16 * j] = s[i][j];
        }
        __syncthreads();

        // O += P V  (contraction over key index)
#pragma unroll
        for (int k = 0; k < 64; k++) {
            float pr[4], vr[4];
#pragma unroll
            for (int i = 0; i < 4; i++) pr[i] = Ps[(ty * 4 + i) * 64 + k];
#pragma unroll
            for (int j = 0; j < 4; j++) vr[j] = Vs[k * 64 + tx + 16 * j];
#pragma unroll
            for (int i = 0; i < 4; i++)
#pragma unroll
                for (int j = 0; j < 4; j++)
                    acc[i][j] = fmaf(pr[i], vr[j], acc[i][j]);
        }
        __syncthreads();
    }

    // Epilogue: divide by l (l=0 -> NaN, matching JAX) and write (B,T,C)
#pragma unroll
    for (int i = 0; i < 4; i++) {
        const int t = q0 + ty * 4 + i;
        float* yp = y + ((size_t)b * T_ + t) * C_ + h * 64;
#pragma unroll
        for (int j = 0; j < 4; j++)
            yp[tx + 16 * j] = acc[i][j] / li[i];
    }
}

// ---------------------------------------------------------------------------
extern "C" void kernel_launch(void* const* d_in, const int* in_sizes, int n_in,
                              void* d_out, int out_size)
{
    const float* x  = (const float*)d_in[0];
    const uint32_t* dmask = (const uint32_t*)d_in[1];
    // d_in[2] = causal_mask: unused (computed analytically in-kernel)
    const float* Wq = (const float*)d_in[3];
    const float* bq = (const float*)d_in[4];
    const float* Wk = (const float*)d_in[5];
    const float* bk = (const float*)d_in[6];
    const float* Wv = (const float*)d_in[7];
    const float* bv = (const float*)d_in[8];
    const float* Wo = (const float*)d_in[9];
    const float* bo = (const float*)d_in[10];

    float *qp, *kp, *vp, *yp;
    cudaGetSymbolAddress((void**)&qp, g_q);
    cudaGetSymbolAddress((void**)&kp, g_k);
    cudaGetSymbolAddress((void**)&vp, g_v);
    cudaGetSymbolAddress((void**)&yp, g_y);

    const dim3 gg(C_ / 128, (B_ * T_) / 128);   // (8, 32)
    sgemm_nt<0><<<gg, 256>>>(x, Wq, bq, qp);
    sgemm_nt<0><<<gg, 256>>>(x, Wk, bk, kp);
    sgemm_nt<0><<<gg, 256>>>(x, Wv, bv, vp);

    const int smem = (64 * 64 + 64 * 65 + 64 * 64 + 64 * 64) * (int)sizeof(float);
    cudaFuncSetAttribute(attn_kernel, cudaFuncAttributeMaxDynamicSharedMemorySize, smem);
    attn_kernel<<<dim3(T_ / 64, H_, B_), 256, smem>>>(dmask, yp);

    sgemm_nt<1><<<gg, 256>>>(yp, Wo, bo, (float*)d_out);
}

// round 4
// speedup vs baseline: 1.4158x; 1.4158x over previous
#include <cuda_runtime.h>
#include <cuda_bf16.h>
#include <mma.h>
#include <math.h>
#include <stdint.h>

using namespace nvcuda;

#define B_ 2
#define T_ 2048
#define C_ 1024
#define H_ 16
#define D_ 64
#define MTOT (B_*T_)          // 4096

// ---------------- scratch (__device__ globals; no allocs allowed) ----------
__device__ float g_q[B_*H_*T_*D_];
__device__ float g_k[B_*H_*T_*D_];
__device__ float g_v[B_*H_*T_*D_];
__device__ __nv_bfloat16 g_ah[MTOT*C_];      // x split hi
__device__ __nv_bfloat16 g_al[MTOT*C_];      // x split lo
__device__ __nv_bfloat16 g_wh[4*C_*C_];      // Wq,Wk,Wv,Wo hi
__device__ __nv_bfloat16 g_wl[4*C_*C_];      // lo
__device__ __nv_bfloat16 g_yh[MTOT*C_];      // attn out split hi
__device__ __nv_bfloat16 g_yl[MTOT*C_];      // lo

// ---------------- helpers --------------------------------------------------
__device__ __forceinline__ uint32_t smem_u32(const void* p) {
    uint32_t a;
    asm("{ .reg .u64 t; cvta.to.shared.u64 t, %1; cvt.u32.u64 %0, t; }" : "=r"(a) : "l"(p));
    return a;
}
__device__ __forceinline__ void cp_async16(uint32_t dst, const void* src) {
    asm volatile("cp.async.cg.shared.global [%0], [%1], 16;" :: "r"(dst), "l"(src) : "memory");
}

// ---------------- split fp32 -> bf16 hi/lo ---------------------------------
__global__ void split_kernel(const float* __restrict__ in,
                             __nv_bfloat16* __restrict__ hi,
                             __nv_bfloat16* __restrict__ lo, int n4)
{
    const int i = blockIdx.x * blockDim.x + threadIdx.x;
    if (i >= n4) return;
    float4 v = ((const float4*)in)[i];
    __nv_bfloat16 h0 = __float2bfloat16_rn(v.x);
    __nv_bfloat16 h1 = __float2bfloat16_rn(v.y);
    __nv_bfloat16 h2 = __float2bfloat16_rn(v.z);
    __nv_bfloat16 h3 = __float2bfloat16_rn(v.w);
    __nv_bfloat16 l0 = __float2bfloat16_rn(v.x - __bfloat162float(h0));
    __nv_bfloat16 l1 = __float2bfloat16_rn(v.y - __bfloat162float(h1));
    __nv_bfloat16 l2 = __float2bfloat16_rn(v.z - __bfloat162float(h2));
    __nv_bfloat16 l3 = __float2bfloat16_rn(v.w - __bfloat162float(h3));
    __nv_bfloat162* hp = (__nv_bfloat162*)hi;
    __nv_bfloat162* lp = (__nv_bfloat162*)lo;
    hp[2*i]   = __nv_bfloat162(h0, h1);
    hp[2*i+1] = __nv_bfloat162(h2, h3);
    lp[2*i]   = __nv_bfloat162(l0, l1);
    lp[2*i+1] = __nv_bfloat162(l2, l3);
}

// ---------------- WMMA bf16-split GEMM -------------------------------------
// out[m,n] = sum_k A[m,k]*W[n,k] + bias[n]; A=(4096,1024), W=(1024,1024).
// A ~ Ah+Al, W ~ Wh+Wl (bf16); out = AhWh + AhWl + AlWh in fp32 accum.
// Block tile 128x128, 8 warps of 32x64, K-slab 32, cp.async double buffer.
// MODE 0: scatter out to (B,H,T,D).  MODE 1: row-major (M,1024).
#define KS 32
#define LDS 40                       // bf16 elems per smem row (32 + 8 pad)
#define SLAB_ELEMS (128*LDS)         // one operand array
#define SLAB_BYTES (SLAB_ELEMS*2)    // 10240
#define STAGE_BYTES (4*SLAB_BYTES)   // 40960
#define GSMEM (2*STAGE_BYTES)        // 81920

template<int MODE>
__global__ __launch_bounds__(256, 1)
void gemm_wmma(const __nv_bfloat16* __restrict__ Ah, const __nv_bfloat16* __restrict__ Al,
               const __nv_bfloat16* __restrict__ Bh, const __nv_bfloat16* __restrict__ Bl,
               const float* __restrict__ bias, float* __restrict__ out)
{
    extern __shared__ char dynsmem[];
    __nv_bfloat16* stage = (__nv_bfloat16*)dynsmem;   // [2][4][128][LDS]
    float* osm = (float*)dynsmem;                     // epilogue [128][128]
    const uint32_t sb = smem_u32(dynsmem);

    const int tid = threadIdx.x;
    const int wid = tid >> 5;
    const int n0 = blockIdx.x * 128;
    const int m0 = blockIdx.y * 128;
    const int warp_m = wid >> 1;      // 0..3
    const int warp_n = wid & 1;       // 0..1

    // issue one K-slab (4 arrays x 128 rows x 64B) into stage buffer b
    auto issue = [&](int s, int b) {
        const int c0 = s * KS;
#pragma unroll
        for (int i = 0; i < 8; i++) {
            const int arr = i >> 1;                       // 0=Ah 1=Al 2=Bh 3=Bl
            const int rem = ((i & 1) << 8) + tid;         // 0..511
            const int r = rem >> 2;                       // 0..127
            const int ch = rem & 3;                       // 16B chunk
            const __nv_bfloat16* g = (arr == 0) ? Ah : (arr == 1) ? Al : (arr == 2) ? Bh : Bl;
            const int row = ((arr < 2) ? m0 : n0) + r;
            const void* gp = g + (size_t)row * 1024 + c0 + ch * 8;
            const uint32_t dst = sb + b * STAGE_BYTES + arr * SLAB_BYTES + r * (LDS * 2) + ch * 16;
            cp_async16(dst, gp);
        }
        asm volatile("cp.async.commit_group;" ::: "memory");
    };

    wmma::fragment<wmma::accumulator, 16, 16, 16, float> fc[2][4];
#pragma unroll
    for (int i = 0; i < 2; i++)
#pragma unroll
        for (int j = 0; j < 4; j++) wmma::fill_fragment(fc[i][j], 0.f);

    issue(0, 0);

    const int NS = 1024 / KS;   // 32
    for (int s = 0; s < NS; s++) {
        const int buf = s & 1;
        if (s + 1 < NS) {
            issue(s + 1, buf ^ 1);
            asm volatile("cp.async.wait_group 1;" ::: "memory");
        } else {
            asm volatile("cp.async.wait_group 0;" ::: "memory");
        }
        __syncthreads();

        const __nv_bfloat16* Ah_s = stage + buf * (4 * SLAB_ELEMS);
        const __nv_bfloat16* Al_s = Ah_s + SLAB_ELEMS;
        const __nv_bfloat16* Bh_s = Al_s + SLAB_ELEMS;
        const __nv_bfloat16* Bl_s = Bh_s + SLAB_ELEMS;

#pragma unroll
        for (int ks = 0; ks < KS; ks += 16) {
            wmma::fragment<wmma::matrix_a, 16, 16, 16, __nv_bfloat16, wmma::row_major> fah[2], fal[2];
            wmma::fragment<wmma::matrix_b, 16, 16, 16, __nv_bfloat16, wmma::col_major> fbh[4], fbl[4];
#pragma unroll
            for (int i = 0; i < 2; i++) {
                wmma::load_matrix_sync(fah[i], Ah_s + (warp_m * 32 + 16 * i) * LDS + ks, LDS);
                wmma::load_matrix_sync(fal[i], Al_s + (warp_m * 32 + 16 * i) * LDS + ks, LDS);
            }
#pragma unroll
            for (int j = 0; j < 4; j++) {
                wmma::load_matrix_sync(fbh[j], Bh_s + (warp_n * 64 + 16 * j) * LDS + ks, LDS);
                wmma::load_matrix_sync(fbl[j], Bl_s + (warp_n * 64 + 16 * j) * LDS + ks, LDS);
            }
#pragma unroll
            for (int i = 0; i < 2; i++)
#pragma unroll
                for (int j = 0; j < 4; j++) {
                    wmma::mma_sync(fc[i][j], fah[i], fbh[j], fc[i][j]);
                    wmma::mma_sync(fc[i][j], fah[i], fbl[j], fc[i][j]);
                    wmma::mma_sync(fc[i][j], fal[i], fbh[j], fc[i][j]);
                }
        }
        __syncthreads();   // protect buf before next issue overwrites it
    }

    // Epilogue: frags -> smem -> bias + layout scatter
#pragma unroll
    for (int i = 0; i < 2; i++)
#pragma unroll
        for (int j = 0; j < 4; j++)
            wmma::store_matrix_sync(osm + (warp_m * 32 + 16 * i) * 128 + warp_n * 64 + 16 * j,
                                    fc[i][j], 128, wmma::mem_row_major);
    __syncthreads();

    for (int idx4 = tid; idx4 < 128 * 32; idx4 += 256) {
        const int r = idx4 >> 5;
        const int c = (idx4 & 31) << 2;
        float4 v = *(float4*)&osm[r * 128 + c];
        const int n = n0 + c;
        v.x += bias[n + 0]; v.y += bias[n + 1]; v.z += bias[n + 2]; v.w += bias[n + 3];
        const int m = m0 + r;
        if (MODE == 0) {
            const int bb = m >> 11, tt = m & (T_ - 1);
            const int hh = n >> 6,  dd = n & 63;
            *(float4*)(out + (((size_t)bb * H_ + hh) * T_ + tt) * D_ + dd) = v;
        } else {
            *(float4*)(out + (size_t)m * C_ + n) = v;
        }
    }
}

// ---------------- analytic causal/step mask --------------------------------
__device__ __forceinline__ bool causal_masked(int q, int k) {
    const bool step = (q >> 5) == (k >> 5);
    const bool tri  = (k <= q) && ((q & 3) != 3) && ((k & 3) != 3);
    return !(step || tri);
}

// ---------------- fused masked flash attention (round-2 core) --------------
__global__ __launch_bounds__(256)
void attn_kernel(const uint32_t* __restrict__ dmask,
                 __nv_bfloat16* __restrict__ yh, __nv_bfloat16* __restrict__ yl)
{
    extern __shared__ char dynsmem[];
    float* sm = (float*)dynsmem;
    float* Qs = sm;            // [64][64]
    float* Ks = Qs + 64 * 64;  // [64][65]
    float* Vs = Ks + 64 * 65;  // [64][64]
    float* Ps = Vs + 64 * 64;  // [64][64]

    const int b  = blockIdx.z;
    const int h  = blockIdx.y;
    const int qi = (int)gridDim.x - 1 - (int)blockIdx.x;
    const int q0 = qi * 64;

    const int tid = threadIdx.x;
    const int ty = tid >> 4;
    const int tx = tid & 15;

    const float* qg = g_q + (((size_t)b * H_ + h) * T_ + q0) * D_;
    const float* kg = g_k + (((size_t)b * H_ + h) * T_) * D_;
    const float* vg = g_v + (((size_t)b * H_ + h) * T_) * D_;

#pragma unroll
    for (int i = 0; i < 4; i++) {
        const int lin = tid + i * 256;
        const int r = lin >> 4, c = (lin & 15) << 2;
        *(float4*)&Qs[r * 64 + c] = *(const float4*)&qg[(size_t)r * 64 + c];
    }

    float mi[4], li[4], acc[4][4];
#pragma unroll
    for (int i = 0; i < 4; i++) {
        mi[i] = -INFINITY; li[i] = 0.f;
#pragma unroll
        for (int j = 0; j < 4; j++) acc[i][j] = 0.f;
    }

    const int ntiles = qi + 1;
    for (int kt = 0; kt < ntiles; kt++) {
        const int k0 = kt * 64;
#pragma unroll
        for (int i = 0; i < 4; i++) {
            const int lin = tid + i * 256;
            const int r = lin >> 4, c = (lin & 15) << 2;
            float4 kv = *(const float4*)&kg[(size_t)(k0 + r) * 64 + c];
            Ks[r * 65 + c + 0] = kv.x;
            Ks[r * 65 + c + 1] = kv.y;
            Ks[r * 65 + c + 2] = kv.z;
            Ks[r * 65 + c + 3] = kv.w;
            *(float4*)&Vs[r * 64 + c] = *(const float4*)&vg[(size_t)(k0 + r) * 64 + c];
        }
        __syncthreads();

        float s[4][4];
#pragma unroll
        for (int i = 0; i < 4; i++)
#pragma unroll
            for (int j = 0; j < 4; j++) s[i][j] = 0.f;
#pragma unroll
        for (int k = 0; k < 64; k++) {
            float qr[4], kr[4];
#pragma unroll
            for (int i = 0; i < 4; i++) qr[i] = Qs[(ty * 4 + i) * 64 + k];
#pragma unroll
            for (int j = 0; j < 4; j++) kr[j] = Ks[(tx + 16 * j) * 65 + k];
#pragma unroll
            for (int i = 0; i < 4; i++)
#pragma unroll
                for (int j = 0; j < 4; j++)
                    s[i][j] = fmaf(qr[i], kr[j], s[i][j]);
        }

        const uint32_t* dmp = dmask + ((size_t)b * T_ + q0) * T_ + k0;
#pragma unroll
        for (int i = 0; i < 4; i++) {
            const int r = ty * 4 + i;
            const int q = q0 + r;
#pragma unroll
            for (int j = 0; j < 4; j++) {
                const int c = tx + 16 * j;
                const int k = k0 + c;
                const bool mk = (dmp[(size_t)r * T_ + c] != 0u) || causal_masked(q, k);
                s[i][j] = mk ? -INFINITY : s[i][j] * 0.125f;
            }
        }

#pragma unroll
        for (int i = 0; i < 4; i++) {
            float mt = fmaxf(fmaxf(s[i][0], s[i][1]), fmaxf(s[i][2], s[i][3]));
            mt = fmaxf(mt, __shfl_xor_sync(0xffffffffu, mt, 8));
            mt = fmaxf(mt, __shfl_xor_sync(0xffffffffu, mt, 4));
            mt = fmaxf(mt, __shfl_xor_sync(0xffffffffu, mt, 2));
            mt = fmaxf(mt, __shfl_xor_sync(0xffffffffu, mt, 1));
            const float mnew = fmaxf(mi[i], mt);
            float alpha, rs = 0.f;
            if (mnew == -INFINITY) {
                alpha = 1.f;
#pragma unroll
                for (int j = 0; j < 4; j++) s[i][j] = 0.f;
            } else {
                alpha = __expf(mi[i] - mnew);
#pragma unroll
                for (int j = 0; j < 4; j++) {
                    s[i][j] = __expf(s[i][j] - mnew);
                    rs += s[i][j];
                }
            }
            rs += __shfl_xor_sync(0xffffffffu, rs, 8);
            rs += __shfl_xor_sync(0xffffffffu, rs, 4);
            rs += __shfl_xor_sync(0xffffffffu, rs, 2);
            rs += __shfl_xor_sync(0xffffffffu, rs, 1);
            li[i] = li[i] * alpha + rs;
            mi[i] = mnew;
#pragma unroll
            for (int j = 0; j < 4; j++) acc[i][j] *= alpha;
            const int r = ty * 4 + i;
#pragma unroll
            for (int j = 0; j < 4; j++) Ps[r * 64 + tx + 16 * j] = s[i][j];
        }
        __syncthreads();

#pragma unroll
        for (int k = 0; k < 64; k++) {
            float pr[4], vr[4];
#pragma unroll
            for (int i = 0; i < 4; i++) pr[i] = Ps[(ty * 4 + i) * 64 + k];
#pragma unroll
            for (int j = 0; j < 4; j++) vr[j] = Vs[k * 64 + tx + 16 * j];
#pragma unroll
            for (int i = 0; i < 4; i++)
#pragma unroll
                for (int j = 0; j < 4; j++)
                    acc[i][j] = fmaf(pr[i], vr[j], acc[i][j]);
        }
        __syncthreads();
    }

    // Epilogue: y -> bf16 hi/lo for the O projection (NaN rows propagate)
#pragma unroll
    for (int i = 0; i < 4; i++) {
        const int t = q0 + ty * 4 + i;
        const size_t base = ((size_t)b * T_ + t) * C_ + h * 64;
#pragma unroll
        for (int j = 0; j < 4; j++) {
            const float val = acc[i][j] / li[i];
            const __nv_bfloat16 hh = __float2bfloat16_rn(val);
            const __nv_bfloat16 ll = __float2bfloat16_rn(val - __bfloat162float(hh));
            yh[base + tx + 16 * j] = hh;
            yl[base + tx + 16 * j] = ll;
        }
    }
}

// ---------------------------------------------------------------------------
extern "C" void kernel_launch(void* const* d_in, const int* in_sizes, int n_in,
                              void* d_out, int out_size)
{
    const float* x  = (const float*)d_in[0];
    const uint32_t* dmask = (const uint32_t*)d_in[1];
    const float* Wq = (const float*)d_in[3];
    const float* bq = (const float*)d_in[4];
    const float* Wk = (const float*)d_in[5];
    const float* bk = (const float*)d_in[6];
    const float* Wv = (const float*)d_in[7];
    const float* bv = (const float*)d_in[8];
    const float* Wo = (const float*)d_in[9];
    const float* bo = (const float*)d_in[10];

    float *qp, *kp, *vp;
    __nv_bfloat16 *ah, *al, *wh, *wl, *yh, *yl;
    cudaGetSymbolAddress((void**)&qp, g_q);
    cudaGetSymbolAddress((void**)&kp, g_k);
    cudaGetSymbolAddress((void**)&vp, g_v);
    cudaGetSymbolAddress((void**)&ah, g_ah);
    cudaGetSymbolAddress((void**)&al, g_al);
    cudaGetSymbolAddress((void**)&wh, g_wh);
    cudaGetSymbolAddress((void**)&wl, g_wl);
    cudaGetSymbolAddress((void**)&yh, g_yh);
    cudaGetSymbolAddress((void**)&yl, g_yl);

    // splits
    split_kernel<<<(MTOT * C_ / 4 + 255) / 256, 256>>>(x, ah, al, MTOT * C_ / 4);
    const int wn4 = C_ * C_ / 4;
    split_kernel<<<(wn4 + 255) / 256, 256>>>(Wq, wh + 0 * C_ * C_, wl + 0 * C_ * C_, wn4);
    split_kernel<<<(wn4 + 255) / 256, 256>>>(Wk, wh + 1 * C_ * C_, wl + 1 * C_ * C_, wn4);
    split_kernel<<<(wn4 + 255) / 256, 256>>>(Wv, wh + 2 * C_ * C_, wl + 2 * C_ * C_, wn4);
    split_kernel<<<(wn4 + 255) / 256, 256>>>(Wo, wh + 3 * C_ * C_, wl + 3 * C_ * C_, wn4);

    cudaFuncSetAttribute(gemm_wmma<0>, cudaFuncAttributeMaxDynamicSharedMemorySize, GSMEM);
    cudaFuncSetAttribute(gemm_wmma<1>, cudaFuncAttributeMaxDynamicSharedMemorySize, GSMEM);

    const dim3 gg(C_ / 128, MTOT / 128);             // (8, 32)
    gemm_wmma<0><<<gg, 256, GSMEM>>>(ah, al, wh + 0 * C_ * C_, wl + 0 * C_ * C_, bq, qp);
    gemm_wmma<0><<<gg, 256, GSMEM>>>(ah, al, wh + 1 * C_ * C_, wl + 1 * C_ * C_, bk, kp);
    gemm_wmma<0><<<gg, 256, GSMEM>>>(ah, al, wh + 2 * C_ * C_, wl + 2 * C_ * C_, bv, vp);

    const int asmem = (64 * 64 + 64 * 65 + 64 * 64 + 64 * 64) * (int)sizeof(float);
    cudaFuncSetAttribute(attn_kernel, cudaFuncAttributeMaxDynamicSharedMemorySize, asmem);
    attn_kernel<<<dim3(T_ / 64, H_, B_), 256, asmem>>>(dmask, yh, yl);

    gemm_wmma<1><<<gg, 256, GSMEM>>>(yh, yl, wh + 3 * C_ * C_, wl + 3 * C_ * C_, bo, (float*)d_out);
}

// round 5
// speedup vs baseline: 1.5827x; 1.1179x over previous
#include <cuda_runtime.h>
#include <cuda_bf16.h>
#include <mma.h>
#include <math.h>
#include <stdint.h>

using namespace nvcuda;

#define B_ 2
#define T_ 2048
#define C_ 1024
#define H_ 16
#define D_ 64
#define MTOT (B_*T_)          // 4096

typedef __nv_bfloat16 bf16;

// ---------------- scratch (__device__ globals; no allocs allowed) ----------
__device__ bf16 g_qh[B_*H_*T_*D_];
__device__ bf16 g_ql[B_*H_*T_*D_];
__device__ bf16 g_kh[B_*H_*T_*D_];
__device__ bf16 g_kl[B_*H_*T_*D_];
__device__ bf16 g_vh[B_*H_*T_*D_];
__device__ bf16 g_vl[B_*H_*T_*D_];
__device__ bf16 g_ah[MTOT*C_];      // x split hi
__device__ bf16 g_al[MTOT*C_];      // x split lo
__device__ bf16 g_wh[4*C_*C_];      // Wq,Wk,Wv,Wo hi
__device__ bf16 g_wl[4*C_*C_];      // lo
__device__ bf16 g_yh[MTOT*C_];      // attn out split hi
__device__ bf16 g_yl[MTOT*C_];      // lo

// ---------------- helpers --------------------------------------------------
__device__ __forceinline__ uint32_t smem_u32(const void* p) {
    uint32_t a;
    asm("{ .reg .u64 t; cvta.to.shared.u64 t, %1; cvt.u32.u64 %0, t; }" : "=r"(a) : "l"(p));
    return a;
}
__device__ __forceinline__ void cp_async16(uint32_t dst, const void* src) {
    asm volatile("cp.async.cg.shared.global [%0], [%1], 16;" :: "r"(dst), "l"(src) : "memory");
}

// ---------------- split fp32 -> bf16 hi/lo ---------------------------------
__global__ void split_kernel(const float* __restrict__ in,
                             bf16* __restrict__ hi, bf16* __restrict__ lo, int n4)
{
    const int i = blockIdx.x * blockDim.x + threadIdx.x;
    if (i >= n4) return;
    float4 v = ((const float4*)in)[i];
    bf16 h0 = __float2bfloat16_rn(v.x);
    bf16 h1 = __float2bfloat16_rn(v.y);
    bf16 h2 = __float2bfloat16_rn(v.z);
    bf16 h3 = __float2bfloat16_rn(v.w);
    bf16 l0 = __float2bfloat16_rn(v.x - __bfloat162float(h0));
    bf16 l1 = __float2bfloat16_rn(v.y - __bfloat162float(h1));
    bf16 l2 = __float2bfloat16_rn(v.z - __bfloat162float(h2));
    bf16 l3 = __float2bfloat16_rn(v.w - __bfloat162float(h3));
    __nv_bfloat162* hp = (__nv_bfloat162*)hi;
    __nv_bfloat162* lp = (__nv_bfloat162*)lo;
    hp[2*i]   = __nv_bfloat162(h0, h1);
    hp[2*i+1] = __nv_bfloat162(h2, h3);
    lp[2*i]   = __nv_bfloat162(l0, l1);
    lp[2*i+1] = __nv_bfloat162(l2, l3);
}

// ---------------- WMMA bf16-split GEMM -------------------------------------
// out[m,n] = sum_k A[m,k]*W[n,k] + bias[n]
// MODE 0: write bf16 hi/lo scattered to (B,H,T,D).  MODE 1: fp32 row-major.
#define KS 32
#define LDSG 40
#define SLAB_ELEMS (128*LDSG)
#define SLAB_BYTES (SLAB_ELEMS*2)
#define STAGE_BYTES (4*SLAB_BYTES)
#define GSMEM (2*STAGE_BYTES)

template<int MODE>
__global__ __launch_bounds__(256, 1)
void gemm_wmma(const bf16* __restrict__ Ah, const bf16* __restrict__ Al,
               const bf16* __restrict__ Bh, const bf16* __restrict__ Bl,
               const float* __restrict__ bias,
               float* __restrict__ out_f, bf16* __restrict__ out_h, bf16* __restrict__ out_l)
{
    extern __shared__ char dynsmem[];
    bf16* stage = (bf16*)dynsmem;
    float* osm = (float*)dynsmem;
    const uint32_t sb = smem_u32(dynsmem);

    const int tid = threadIdx.x;
    const int wid = tid >> 5;
    const int n0 = blockIdx.x * 128;
    const int m0 = blockIdx.y * 128;
    const int warp_m = wid >> 1;
    const int warp_n = wid & 1;

    auto issue = [&](int s, int b) {
        const int c0 = s * KS;
#pragma unroll
        for (int i = 0; i < 8; i++) {
            const int arr = i >> 1;
            const int rem = ((i & 1) << 8) + tid;
            const int r = rem >> 2;
            const int ch = rem & 3;
            const bf16* g = (arr == 0) ? Ah : (arr == 1) ? Al : (arr == 2) ? Bh : Bl;
            const int row = ((arr < 2) ? m0 : n0) + r;
            const void* gp = g + (size_t)row * 1024 + c0 + ch * 8;
            const uint32_t dst = sb + b * STAGE_BYTES + arr * SLAB_BYTES + r * (LDSG * 2) + ch * 16;
            cp_async16(dst, gp);
        }
        asm volatile("cp.async.commit_group;" ::: "memory");
    };

    wmma::fragment<wmma::accumulator, 16, 16, 16, float> fc[2][4];
#pragma unroll
    for (int i = 0; i < 2; i++)
#pragma unroll
        for (int j = 0; j < 4; j++) wmma::fill_fragment(fc[i][j], 0.f);

    issue(0, 0);

    const int NS = 1024 / KS;
    for (int s = 0; s < NS; s++) {
        const int buf = s & 1;
        if (s + 1 < NS) {
            issue(s + 1, buf ^ 1);
            asm volatile("cp.async.wait_group 1;" ::: "memory");
        } else {
            asm volatile("cp.async.wait_group 0;" ::: "memory");
        }
        __syncthreads();

        const bf16* Ah_s = stage + buf * (4 * SLAB_ELEMS);
        const bf16* Al_s = Ah_s + SLAB_ELEMS;
        const bf16* Bh_s = Al_s + SLAB_ELEMS;
        const bf16* Bl_s = Bh_s + SLAB_ELEMS;

#pragma unroll
        for (int ks = 0; ks < KS; ks += 16) {
            wmma::fragment<wmma::matrix_a, 16, 16, 16, bf16, wmma::row_major> fah[2], fal[2];
            wmma::fragment<wmma::matrix_b, 16, 16, 16, bf16, wmma::col_major> fbh[4], fbl[4];
#pragma unroll
            for (int i = 0; i < 2; i++) {
                wmma::load_matrix_sync(fah[i], Ah_s + (warp_m * 32 + 16 * i) * LDSG + ks, LDSG);
                wmma::load_matrix_sync(fal[i], Al_s + (warp_m * 32 + 16 * i) * LDSG + ks, LDSG);
            }
#pragma unroll
            for (int j = 0; j < 4; j++) {
                wmma::load_matrix_sync(fbh[j], Bh_s + (warp_n * 64 + 16 * j) * LDSG + ks, LDSG);
                wmma::load_matrix_sync(fbl[j], Bl_s + (warp_n * 64 + 16 * j) * LDSG + ks, LDSG);
            }
#pragma unroll
            for (int i = 0; i < 2; i++)
#pragma unroll
                for (int j = 0; j < 4; j++) {
                    wmma::mma_sync(fc[i][j], fah[i], fbh[j], fc[i][j]);
                    wmma::mma_sync(fc[i][j], fah[i], fbl[j], fc[i][j]);
                    wmma::mma_sync(fc[i][j], fal[i], fbh[j], fc[i][j]);
                }
        }
        __syncthreads();
    }

#pragma unroll
    for (int i = 0; i < 2; i++)
#pragma unroll
        for (int j = 0; j < 4; j++)
            wmma::store_matrix_sync(osm + (warp_m * 32 + 16 * i) * 128 + warp_n * 64 + 16 * j,
                                    fc[i][j], 128, wmma::mem_row_major);
    __syncthreads();

    for (int idx4 = tid; idx4 < 128 * 32; idx4 += 256) {
        const int r = idx4 >> 5;
        const int c = (idx4 & 31) << 2;
        float4 v = *(float4*)&osm[r * 128 + c];
        const int n = n0 + c;
        v.x += bias[n + 0]; v.y += bias[n + 1]; v.z += bias[n + 2]; v.w += bias[n + 3];
        const int m = m0 + r;
        if (MODE == 0) {
            const int bb = m >> 11, tt = m & (T_ - 1);
            const int hh = n >> 6,  dd = n & 63;
            const size_t off = (((size_t)bb * H_ + hh) * T_ + tt) * D_ + dd;
            bf16 h0 = __float2bfloat16_rn(v.x), h1 = __float2bfloat16_rn(v.y);
            bf16 h2 = __float2bfloat16_rn(v.z), h3 = __float2bfloat16_rn(v.w);
            bf16 l0 = __float2bfloat16_rn(v.x - __bfloat162float(h0));
            bf16 l1 = __float2bfloat16_rn(v.y - __bfloat162float(h1));
            bf16 l2 = __float2bfloat16_rn(v.z - __bfloat162float(h2));
            bf16 l3 = __float2bfloat16_rn(v.w - __bfloat162float(h3));
            *(__nv_bfloat162*)(out_h + off)     = __nv_bfloat162(h0, h1);
            *(__nv_bfloat162*)(out_h + off + 2) = __nv_bfloat162(h2, h3);
            *(__nv_bfloat162*)(out_l + off)     = __nv_bfloat162(l0, l1);
            *(__nv_bfloat162*)(out_l + off + 2) = __nv_bfloat162(l2, l3);
        } else {
            *(float4*)(out_f + (size_t)m * C_ + n) = v;
        }
    }
}

// ---------------- analytic causal/step mask --------------------------------
__device__ __forceinline__ bool causal_masked(int q, int k) {
    const bool step = (q >> 5) == (k >> 5);
    const bool tri  = (k <= q) && ((q & 3) != 3) && ((k & 3) != 3);
    return !(step || tri);
}

// ---------------- WMMA flash attention -------------------------------------
// S = QK^T and U = PV via bf16-split HMMA; softmax/mask/rescale SIMT.
#define SBQ 72   // bf16 row stride (144B): ldmatrix conflict-free
#define SFQ 68   // fp32 row stride
#define QH_OFF 0
#define QL_OFF 9216
#define KH_OFF 18432
#define KL_OFF 27648
#define VH_OFF 36864
#define VL_OFF 46080
#define PH_OFF 55296
#define PL_OFF 64512
#define SS_OFF 73728
#define US_OFF 91136
#define ASMEM  108544

__global__ __launch_bounds__(256, 1)
void attn_wmma(const uint32_t* __restrict__ dmask,
               bf16* __restrict__ yh, bf16* __restrict__ yl)
{
    extern __shared__ char dynsmem[];
    const uint32_t sb = smem_u32(dynsmem);
    bf16* Qh = (bf16*)(dynsmem + QH_OFF);
    bf16* Ql = (bf16*)(dynsmem + QL_OFF);
    bf16* Ksh = (bf16*)(dynsmem + KH_OFF);
    bf16* Ksl = (bf16*)(dynsmem + KL_OFF);
    bf16* Vsh = (bf16*)(dynsmem + VH_OFF);
    bf16* Vsl = (bf16*)(dynsmem + VL_OFF);
    bf16* Ph = (bf16*)(dynsmem + PH_OFF);
    bf16* Pl = (bf16*)(dynsmem + PL_OFF);
    float* Ss = (float*)(dynsmem + SS_OFF);
    float* Us = (float*)(dynsmem + US_OFF);

    const int b  = blockIdx.z;
    const int h  = blockIdx.y;
    const int qi = (int)gridDim.x - 1 - (int)blockIdx.x;
    const int q0 = qi * 64;

    const int tid = threadIdx.x;
    const int wid = tid >> 5;
    const int warp_m = wid >> 1;   // 0..3
    const int warp_n = wid & 1;    // 0..1
    const int ty = tid >> 4;
    const int tx = tid & 15;

    const size_t headoff = ((size_t)b * H_ + h) * T_;
    const bf16* qhg = g_qh + (headoff + q0) * D_;
    const bf16* qlg = g_ql + (headoff + q0) * D_;

    // Q tile: 2 arrays x 64 rows x 8 16B-chunks = 1024 chunks, 4/thread
#pragma unroll
    for (int i = 0; i < 4; i++) {
        const int c = tid + i * 256;
        const int arr = c >> 9;
        const int rem = c & 511;
        const int r = rem >> 3, ch = rem & 7;
        const bf16* g = arr ? qlg : qhg;
        cp_async16(sb + (arr ? QL_OFF : QH_OFF) + r * (SBQ * 2) + ch * 16,
                   g + (size_t)r * D_ + ch * 8);
    }

    float mi[4], li[4], alpha[4], acc[4][4];
#pragma unroll
    for (int i = 0; i < 4; i++) {
        mi[i] = -INFINITY; li[i] = 0.f;
#pragma unroll
        for (int j = 0; j < 4; j++) acc[i][j] = 0.f;
    }

    const int ntiles = qi + 1;
    for (int kt = 0; kt < ntiles; kt++) {
        const int k0 = kt * 64;
        // K,V tiles: 4 arrays x 512 chunks = 2048, 8/thread
#pragma unroll
        for (int i = 0; i < 8; i++) {
            const int c = tid + i * 256;
            const int arr = c >> 9;
            const int rem = c & 511;
            const int r = rem >> 3, ch = rem & 7;
            const bf16* g = (arr == 0) ? g_kh : (arr == 1) ? g_kl : (arr == 2) ? g_vh : g_vl;
            const uint32_t off = (arr == 0) ? KH_OFF : (arr == 1) ? KL_OFF : (arr == 2) ? VH_OFF : VL_OFF;
            cp_async16(sb + off + r * (SBQ * 2) + ch * 16,
                       g + (headoff + k0 + r) * D_ + ch * 8);
        }
        asm volatile("cp.async.commit_group;" ::: "memory");
        asm volatile("cp.async.wait_group 0;" ::: "memory");
        __syncthreads();

        // ---- S = Q K^T (split, 3 products) ----
        {
            wmma::fragment<wmma::accumulator, 16, 16, 16, float> fs[2];
            wmma::fill_fragment(fs[0], 0.f);
            wmma::fill_fragment(fs[1], 0.f);
#pragma unroll
            for (int k = 0; k < 4; k++) {
                wmma::fragment<wmma::matrix_a, 16, 16, 16, bf16, wmma::row_major> fah, fal;
                wmma::load_matrix_sync(fah, Qh + (warp_m * 16) * SBQ + k * 16, SBQ);
                wmma::load_matrix_sync(fal, Ql + (warp_m * 16) * SBQ + k * 16, SBQ);
#pragma unroll
                for (int n = 0; n < 2; n++) {
                    wmma::fragment<wmma::matrix_b, 16, 16, 16, bf16, wmma::col_major> fbh, fbl;
                    wmma::load_matrix_sync(fbh, Ksh + (warp_n * 32 + n * 16) * SBQ + k * 16, SBQ);
                    wmma::load_matrix_sync(fbl, Ksl + (warp_n * 32 + n * 16) * SBQ + k * 16, SBQ);
                    wmma::mma_sync(fs[n], fah, fbh, fs[n]);
                    wmma::mma_sync(fs[n], fah, fbl, fs[n]);
                    wmma::mma_sync(fs[n], fal, fbh, fs[n]);
                }
            }
            wmma::store_matrix_sync(Ss + (warp_m * 16) * SFQ + warp_n * 32,      fs[0], SFQ, wmma::mem_row_major);
            wmma::store_matrix_sync(Ss + (warp_m * 16) * SFQ + warp_n * 32 + 16, fs[1], SFQ, wmma::mem_row_major);
        }
        __syncthreads();

        // ---- SIMT: mask + online softmax; P -> bf16 hi/lo ----
        const uint32_t* dmp = dmask + ((size_t)b * T_ + q0) * T_ + k0;
#pragma unroll
        for (int i = 0; i < 4; i++) {
            const int r = ty * 4 + i;
            const int q = q0 + r;
            float s[4];
#pragma unroll
            for (int j = 0; j < 4; j++) {
                const int c = tx + 16 * j;
                const int k = k0 + c;
                const bool mk = (dmp[(size_t)r * T_ + c] != 0u) || causal_masked(q, k);
                s[j] = mk ? -INFINITY : Ss[r * SFQ + c] * 0.125f;
            }
            float mt = fmaxf(fmaxf(s[0], s[1]), fmaxf(s[2], s[3]));
            mt = fmaxf(mt, __shfl_xor_sync(0xffffffffu, mt, 8));
            mt = fmaxf(mt, __shfl_xor_sync(0xffffffffu, mt, 4));
            mt = fmaxf(mt, __shfl_xor_sync(0xffffffffu, mt, 2));
            mt = fmaxf(mt, __shfl_xor_sync(0xffffffffu, mt, 1));
            const float mnew = fmaxf(mi[i], mt);
            float rs = 0.f;
            if (mnew == -INFINITY) {
                alpha[i] = 1.f;
#pragma unroll
                for (int j = 0; j < 4; j++) s[j] = 0.f;
            } else {
                alpha[i] = __expf(mi[i] - mnew);
#pragma unroll
                for (int j = 0; j < 4; j++) {
                    s[j] = __expf(s[j] - mnew);
                    rs += s[j];
                }
            }
            rs += __shfl_xor_sync(0xffffffffu, rs, 8);
            rs += __shfl_xor_sync(0xffffffffu, rs, 4);
            rs += __shfl_xor_sync(0xffffffffu, rs, 2);
            rs += __shfl_xor_sync(0xffffffffu, rs, 1);
            li[i] = li[i] * alpha[i] + rs;
            mi[i] = mnew;
#pragma unroll
            for (int j = 0; j < 4; j++) {
                const int c = tx + 16 * j;
                const bf16 hh = __float2bfloat16_rn(s[j]);
                Ph[r * SBQ + c] = hh;
                Pl[r * SBQ + c] = __float2bfloat16_rn(s[j] - __bfloat162float(hh));
            }
        }
        __syncthreads();

        // ---- U = P V (split, 3 products) ----
        {
            wmma::fragment<wmma::accumulator, 16, 16, 16, float> fu[2];
            wmma::fill_fragment(fu[0], 0.f);
            wmma::fill_fragment(fu[1], 0.f);
#pragma unroll
            for (int k = 0; k < 4; k++) {
                wmma::fragment<wmma::matrix_a, 16, 16, 16, bf16, wmma::row_major> fph, fpl;
                wmma::load_matrix_sync(fph, Ph + (warp_m * 16) * SBQ + k * 16, SBQ);
                wmma::load_matrix_sync(fpl, Pl + (warp_m * 16) * SBQ + k * 16, SBQ);
#pragma unroll
                for (int n = 0; n < 2; n++) {
                    wmma::fragment<wmma::matrix_b, 16, 16, 16, bf16, wmma::row_major> fvh, fvl;
                    wmma::load_matrix_sync(fvh, Vsh + (k * 16) * SBQ + warp_n * 32 + n * 16, SBQ);
                    wmma::load_matrix_sync(fvl, Vsl + (k * 16) * SBQ + warp_n * 32 + n * 16, SBQ);
                    wmma::mma_sync(fu[n], fph, fvh, fu[n]);
                    wmma::mma_sync(fu[n], fph, fvl, fu[n]);
                    wmma::mma_sync(fu[n], fpl, fvh, fu[n]);
                }
            }
            wmma::store_matrix_sync(Us + (warp_m * 16) * SFQ + warp_n * 32,      fu[0], SFQ, wmma::mem_row_major);
            wmma::store_matrix_sync(Us + (warp_m * 16) * SFQ + warp_n * 32 + 16, fu[1], SFQ, wmma::mem_row_major);
        }
        __syncthreads();

        // ---- SIMT: O = O*alpha + U ----
#pragma unroll
        for (int i = 0; i < 4; i++) {
            const int r = ty * 4 + i;
#pragma unroll
            for (int j = 0; j < 4; j++)
                acc[i][j] = acc[i][j] * alpha[i] + Us[r * SFQ + tx + 16 * j];
        }
        __syncthreads();   // Us/Ph safe before next tile overwrites
    }

    // Epilogue: y -> bf16 hi/lo (li=0 -> NaN, matching JAX)
#pragma unroll
    for (int i = 0; i < 4; i++) {
        const int t = q0 + ty * 4 + i;
        const size_t base = ((size_t)b * T_ + t) * C_ + h * 64;
#pragma unroll
        for (int j = 0; j < 4; j++) {
            const float val = acc[i][j] / li[i];
            const bf16 hh = __float2bfloat16_rn(val);
            yh[base + tx + 16 * j] = hh;
            yl[base + tx + 16 * j] = __float2bfloat16_rn(val - __bfloat162float(hh));
        }
    }
}

// ---------------------------------------------------------------------------
extern "C" void kernel_launch(void* const* d_in, const int* in_sizes, int n_in,
                              void* d_out, int out_size)
{
    const float* x  = (const float*)d_in[0];
    const uint32_t* dmask = (const uint32_t*)d_in[1];
    const float* Wq = (const float*)d_in[3];
    const float* bq = (const float*)d_in[4];
    const float* Wk = (const float*)d_in[5];
    const float* bk = (const float*)d_in[6];
    const float* Wv = (const float*)d_in[7];
    const float* bv = (const float*)d_in[8];
    const float* Wo = (const float*)d_in[9];
    const float* bo = (const float*)d_in[10];

    bf16 *qh, *ql, *kh, *kl, *vh, *vl, *ah, *al, *wh, *wl, *yh, *yl;
    cudaGetSymbolAddress((void**)&qh, g_qh);
    cudaGetSymbolAddress((void**)&ql, g_ql);
    cudaGetSymbolAddress((void**)&kh, g_kh);
    cudaGetSymbolAddress((void**)&kl, g_kl);
    cudaGetSymbolAddress((void**)&vh, g_vh);
    cudaGetSymbolAddress((void**)&vl, g_vl);
    cudaGetSymbolAddress((void**)&ah, g_ah);
    cudaGetSymbolAddress((void**)&al, g_al);
    cudaGetSymbolAddress((void**)&wh, g_wh);
    cudaGetSymbolAddress((void**)&wl, g_wl);
    cudaGetSymbolAddress((void**)&yh, g_yh);
    cudaGetSymbolAddress((void**)&yl, g_yl);

    split_kernel<<<(MTOT * C_ / 4 + 255) / 256, 256>>>(x, ah, al, MTOT * C_ / 4);
    const int wn4 = C_ * C_ / 4;
    split_kernel<<<(wn4 + 255) / 256, 256>>>(Wq, wh + 0 * C_ * C_, wl + 0 * C_ * C_, wn4);
    split_kernel<<<(wn4 + 255) / 256, 256>>>(Wk, wh + 1 * C_ * C_, wl + 1 * C_ * C_, wn4);
    split_kernel<<<(wn4 + 255) / 256, 256>>>(Wv, wh + 2 * C_ * C_, wl + 2 * C_ * C_, wn4);
    split_kernel<<<(wn4 + 255) / 256, 256>>>(Wo, wh + 3 * C_ * C_, wl + 3 * C_ * C_, wn4);

    cudaFuncSetAttribute(gemm_wmma<0>, cudaFuncAttributeMaxDynamicSharedMemorySize, GSMEM);
    cudaFuncSetAttribute(gemm_wmma<1>, cudaFuncAttributeMaxDynamicSharedMemorySize, GSMEM);

    const dim3 gg(C_ / 128, MTOT / 128);
    gemm_wmma<0><<<gg, 256, GSMEM>>>(ah, al, wh + 0 * C_ * C_, wl + 0 * C_ * C_, bq, nullptr, qh, ql);
    gemm_wmma<0><<<gg, 256, GSMEM>>>(ah, al, wh + 1 * C_ * C_, wl + 1 * C_ * C_, bk, nullptr, kh, kl);
    gemm_wmma<0><<<gg, 256, GSMEM>>>(ah, al, wh + 2 * C_ * C_, wl + 2 * C_ * C_, bv, nullptr, vh, vl);

    cudaFuncSetAttribute(attn_wmma, cudaFuncAttributeMaxDynamicSharedMemorySize, ASMEM);
    attn_wmma<<<dim3(T_ / 64, H_, B_), 256, ASMEM>>>(dmask, yh, yl);

    gemm_wmma<1><<<gg, 256, GSMEM>>>(yh, yl, wh + 3 * C_ * C_, wl + 3 * C_ * C_, bo, (float*)d_out, nullptr, nullptr);
}

// round 6
// speedup vs baseline: 1.6340x; 1.0324x over previous
#include <cuda_runtime.h>
#include <cuda_bf16.h>
#include <mma.h>
#include <math.h>
#include <stdint.h>

using namespace nvcuda;

#define B_ 2
#define T_ 2048
#define C_ 1024
#define H_ 16
#define D_ 64
#define MTOT (B_*T_)          // 4096

typedef __nv_bfloat16 bf16;

// ---------------- scratch (__device__ globals; no allocs allowed) ----------
__device__ bf16 g_qh[B_*H_*T_*D_];
__device__ bf16 g_ql[B_*H_*T_*D_];
__device__ bf16 g_kh[B_*H_*T_*D_];
__device__ bf16 g_kl[B_*H_*T_*D_];
__device__ bf16 g_vh[B_*H_*T_*D_];
__device__ bf16 g_vl[B_*H_*T_*D_];
__device__ bf16 g_ah[MTOT*C_];
__device__ bf16 g_al[MTOT*C_];
__device__ bf16 g_wh[4*C_*C_];
__device__ bf16 g_wl[4*C_*C_];
__device__ bf16 g_yh[MTOT*C_];
__device__ bf16 g_yl[MTOT*C_];

// ---------------- helpers --------------------------------------------------
__device__ __forceinline__ uint32_t smem_u32(const void* p) {
    uint32_t a;
    asm("{ .reg .u64 t; cvta.to.shared.u64 t, %1; cvt.u32.u64 %0, t; }" : "=r"(a) : "l"(p));
    return a;
}
__device__ __forceinline__ void cp_async16(uint32_t dst, const void* src) {
    asm volatile("cp.async.cg.shared.global [%0], [%1], 16;" :: "r"(dst), "l"(src) : "memory");
}

// ---------------- split fp32 -> bf16 hi/lo ---------------------------------
__global__ void split_kernel(const float* __restrict__ in,
                             bf16* __restrict__ hi, bf16* __restrict__ lo, int n4)
{
    const int i = blockIdx.x * blockDim.x + threadIdx.x;
    if (i >= n4) return;
    float4 v = ((const float4*)in)[i];
    bf16 h0 = __float2bfloat16_rn(v.x);
    bf16 h1 = __float2bfloat16_rn(v.y);
    bf16 h2 = __float2bfloat16_rn(v.z);
    bf16 h3 = __float2bfloat16_rn(v.w);
    bf16 l0 = __float2bfloat16_rn(v.x - __bfloat162float(h0));
    bf16 l1 = __float2bfloat16_rn(v.y - __bfloat162float(h1));
    bf16 l2 = __float2bfloat16_rn(v.z - __bfloat162float(h2));
    bf16 l3 = __float2bfloat16_rn(v.w - __bfloat162float(h3));
    __nv_bfloat162* hp = (__nv_bfloat162*)hi;
    __nv_bfloat162* lp = (__nv_bfloat162*)lo;
    hp[2*i]   = __nv_bfloat162(h0, h1);
    hp[2*i+1] = __nv_bfloat162(h2, h3);
    lp[2*i]   = __nv_bfloat162(l0, l1);
    lp[2*i+1] = __nv_bfloat162(l2, l3);
}

// ---------------- WMMA bf16-split GEMM -------------------------------------
// MODE 0: grid.z in {0,1,2} selects Wq/Wk/Wv and Q/K/V bf16 hi/lo outputs.
// MODE 1: fp32 row-major output (O projection).
#define KS 32
#define LDSG 40
#define SLAB_ELEMS (128*LDSG)
#define SLAB_BYTES (SLAB_ELEMS*2)
#define STAGE_BYTES (4*SLAB_BYTES)
#define GSMEM (2*STAGE_BYTES)

template<int MODE>
__global__ __launch_bounds__(256, 1)
void gemm_wmma(const bf16* __restrict__ Ah, const bf16* __restrict__ Al,
               const bf16* __restrict__ WhBase, const bf16* __restrict__ WlBase,
               const float* __restrict__ b0, const float* __restrict__ b1,
               const float* __restrict__ b2, float* __restrict__ out_f)
{
    extern __shared__ char dynsmem[];
    bf16* stage = (bf16*)dynsmem;
    float* osm = (float*)dynsmem;
    const uint32_t sb = smem_u32(dynsmem);

    const int z = (MODE == 0) ? (int)blockIdx.z : 0;
    const bf16* Bh = WhBase + (size_t)z * C_ * C_;
    const bf16* Bl = WlBase + (size_t)z * C_ * C_;
    const float* bias = (z == 0) ? b0 : (z == 1) ? b1 : b2;
    bf16* outh = (MODE == 0) ? ((z == 0) ? g_qh : (z == 1) ? g_kh : g_vh) : nullptr;
    bf16* outl = (MODE == 0) ? ((z == 0) ? g_ql : (z == 1) ? g_kl : g_vl) : nullptr;

    const int tid = threadIdx.x;
    const int wid = tid >> 5;
    const int n0 = blockIdx.x * 128;
    const int m0 = blockIdx.y * 128;
    const int warp_m = wid >> 1;
    const int warp_n = wid & 1;

    auto issue = [&](int s, int b) {
        const int c0 = s * KS;
#pragma unroll
        for (int i = 0; i < 8; i++) {
            const int arr = i >> 1;
            const int rem = ((i & 1) << 8) + tid;
            const int r = rem >> 2;
            const int ch = rem & 3;
            const bf16* g = (arr == 0) ? Ah : (arr == 1) ? Al : (arr == 2) ? Bh : Bl;
            const int row = ((arr < 2) ? m0 : n0) + r;
            cp_async16(sb + b * STAGE_BYTES + arr * SLAB_BYTES + r * (LDSG * 2) + ch * 16,
                       g + (size_t)row * 1024 + c0 + ch * 8);
        }
        asm volatile("cp.async.commit_group;" ::: "memory");
    };

    wmma::fragment<wmma::accumulator, 16, 16, 16, float> fc[2][4];
#pragma unroll
    for (int i = 0; i < 2; i++)
#pragma unroll
        for (int j = 0; j < 4; j++) wmma::fill_fragment(fc[i][j], 0.f);

    issue(0, 0);

    const int NS = 1024 / KS;
    for (int s = 0; s < NS; s++) {
        const int buf = s & 1;
        if (s + 1 < NS) {
            issue(s + 1, buf ^ 1);
            asm volatile("cp.async.wait_group 1;" ::: "memory");
        } else {
            asm volatile("cp.async.wait_group 0;" ::: "memory");
        }
        __syncthreads();

        const bf16* Ah_s = stage + buf * (4 * SLAB_ELEMS);
        const bf16* Al_s = Ah_s + SLAB_ELEMS;
        const bf16* Bh_s = Al_s + SLAB_ELEMS;
        const bf16* Bl_s = Bh_s + SLAB_ELEMS;

#pragma unroll
        for (int ks = 0; ks < KS; ks += 16) {
            wmma::fragment<wmma::matrix_a, 16, 16, 16, bf16, wmma::row_major> fah[2], fal[2];
            wmma::fragment<wmma::matrix_b, 16, 16, 16, bf16, wmma::col_major> fbh[4], fbl[4];
#pragma unroll
            for (int i = 0; i < 2; i++) {
                wmma::load_matrix_sync(fah[i], Ah_s + (warp_m * 32 + 16 * i) * LDSG + ks, LDSG);
                wmma::load_matrix_sync(fal[i], Al_s + (warp_m * 32 + 16 * i) * LDSG + ks, LDSG);
            }
#pragma unroll
            for (int j = 0; j < 4; j++) {
                wmma::load_matrix_sync(fbh[j], Bh_s + (warp_n * 64 + 16 * j) * LDSG + ks, LDSG);
                wmma::load_matrix_sync(fbl[j], Bl_s + (warp_n * 64 + 16 * j) * LDSG + ks, LDSG);
            }
#pragma unroll
            for (int i = 0; i < 2; i++)
#pragma unroll
                for (int j = 0; j < 4; j++) {
                    wmma::mma_sync(fc[i][j], fah[i], fbh[j], fc[i][j]);
                    wmma::mma_sync(fc[i][j], fah[i], fbl[j], fc[i][j]);
                    wmma::mma_sync(fc[i][j], fal[i], fbh[j], fc[i][j]);
                }
        }
        __syncthreads();
    }

#pragma unroll
    for (int i = 0; i < 2; i++)
#pragma unroll
        for (int j = 0; j < 4; j++)
            wmma::store_matrix_sync(osm + (warp_m * 32 + 16 * i) * 128 + warp_n * 64 + 16 * j,
                                    fc[i][j], 128, wmma::mem_row_major);
    __syncthreads();

    for (int idx4 = tid; idx4 < 128 * 32; idx4 += 256) {
        const int r = idx4 >> 5;
        const int c = (idx4 & 31) << 2;
        float4 v = *(float4*)&osm[r * 128 + c];
        const int n = n0 + c;
        v.x += bias[n + 0]; v.y += bias[n + 1]; v.z += bias[n + 2]; v.w += bias[n + 3];
        const int m = m0 + r;
        if (MODE == 0) {
            const int bb = m >> 11, tt = m & (T_ - 1);
            const int hh = n >> 6,  dd = n & 63;
            const size_t off = (((size_t)bb * H_ + hh) * T_ + tt) * D_ + dd;
            bf16 h0 = __float2bfloat16_rn(v.x), h1 = __float2bfloat16_rn(v.y);
            bf16 h2 = __float2bfloat16_rn(v.z), h3 = __float2bfloat16_rn(v.w);
            bf16 l0 = __float2bfloat16_rn(v.x - __bfloat162float(h0));
            bf16 l1 = __float2bfloat16_rn(v.y - __bfloat162float(h1));
            bf16 l2 = __float2bfloat16_rn(v.z - __bfloat162float(h2));
            bf16 l3 = __float2bfloat16_rn(v.w - __bfloat162float(h3));
            *(__nv_bfloat162*)(outh + off)     = __nv_bfloat162(h0, h1);
            *(__nv_bfloat162*)(outh + off + 2) = __nv_bfloat162(h2, h3);
            *(__nv_bfloat162*)(outl + off)     = __nv_bfloat162(l0, l1);
            *(__nv_bfloat162*)(outl + off + 2) = __nv_bfloat162(l2, l3);
        } else {
            *(float4*)(out_f + (size_t)m * C_ + n) = v;
        }
    }
}

// ---------------- analytic causal/step mask --------------------------------
__device__ __forceinline__ bool causal_masked(int q, int k) {
    const bool step = (q >> 5) == (k >> 5);
    const bool tri  = (k <= q) && ((q & 3) != 3) && ((k & 3) != 3);
    return !(step || tri);
}

// ---------------- warp-independent WMMA flash attention --------------------
// 128 Q rows/block, 8 warps x 16 rows; K/V double-buffered; no-max softmax;
// O accumulates in persistent WMMA fragments (no rescale needed).
#define SBQ 72              // bf16 row stride (144B)
#define SBQB 144
#define SSW 68              // fp32 staging stride
#define QH_OFF 0
#define QL_OFF 18432
#define KV_OFF 36864
#define KVBUF  36864        // one buffer: Kh,Kl,Vh,Vl each 64*72*2=9216
#define PH_OFF 110592
#define PL_OFF 129024
#define SS_OFF 147456       // per-warp 16*68*4 = 4352
#define ASMEM  182272

__global__ __launch_bounds__(256, 1)
void attn_wmma2(const uint32_t* __restrict__ dmask,
                bf16* __restrict__ yh, bf16* __restrict__ yl)
{
    extern __shared__ char dyn[];
    const uint32_t sb = smem_u32(dyn);
    const int b = blockIdx.z, h = blockIdx.y;
    const int qi = (int)gridDim.x - 1 - (int)blockIdx.x;   // heavy first
    const int q0 = qi * 128;
    const int tid = threadIdx.x, wid = tid >> 5, lane = tid & 31;
    const int r16 = lane >> 1, hf = lane & 1;
    const size_t headoff = ((size_t)b * H_ + h) * T_;

    // Q tile: 2 arrays x 128 rows x 8 chunks = 2048, 8 per thread
    {
        const bf16* qhg = g_qh + (headoff + q0) * D_;
        const bf16* qlg = g_ql + (headoff + q0) * D_;
#pragma unroll
        for (int i = 0; i < 8; i++) {
            const int c = tid + i * 256;
            const int arr = c >> 10;
            const int rem = c & 1023;
            const int r = rem >> 3, ch = rem & 7;
            const bf16* g = arr ? qlg : qhg;
            cp_async16(sb + (arr ? QL_OFF : QH_OFF) + r * SBQB + ch * 16,
                       g + (size_t)r * D_ + ch * 8);
        }
    }

    auto issueKV = [&](int kt, int buf) {
        const int k0 = kt * 64;
#pragma unroll
        for (int i = 0; i < 8; i++) {
            const int c = tid + i * 256;
            const int arr = c >> 9;
            const int rem = c & 511;
            const int r = rem >> 3, ch = rem & 7;
            const bf16* g = (arr == 0) ? g_kh : (arr == 1) ? g_kl : (arr == 2) ? g_vh : g_vl;
            cp_async16(sb + KV_OFF + buf * KVBUF + arr * 9216 + r * SBQB + ch * 16,
                       g + (headoff + k0 + r) * D_ + ch * 8);
        }
        asm volatile("cp.async.commit_group;" ::: "memory");
    };

    issueKV(0, 0);
    asm volatile("cp.async.wait_group 0;" ::: "memory");
    __syncthreads();

    wmma::fragment<wmma::accumulator, 16, 16, 16, float> fo[4];
#pragma unroll
    for (int n = 0; n < 4; n++) wmma::fill_fragment(fo[n], 0.f);
    float li = 0.f;

    const bf16* Qh = (const bf16*)(dyn + QH_OFF) + wid * 16 * SBQ;
    const bf16* Ql = (const bf16*)(dyn + QL_OFF) + wid * 16 * SBQ;
    bf16* Ph = (bf16*)(dyn + PH_OFF) + wid * 16 * SBQ;
    bf16* Pl = (bf16*)(dyn + PL_OFF) + wid * 16 * SBQ;
    float* Ssw = (float*)(dyn + SS_OFF + wid * 4352);

    const int nt = 2 * qi + 2;
    for (int s = 0; s < nt; s++) {
        const int buf = s & 1;
        if (s + 1 < nt) issueKV(s + 1, buf ^ 1);

        const bf16* Kh = (const bf16*)(dyn + KV_OFF + buf * KVBUF);
        const bf16* Kl = Kh + 4608;
        const bf16* Vh = Kh + 9216;
        const bf16* Vl = Kh + 13824;
        const int k0 = s * 64;

        // ---- S = Q K^T (split, 3 products), warp-private 16x64 ----
        wmma::fragment<wmma::accumulator, 16, 16, 16, float> fs[4];
#pragma unroll
        for (int n = 0; n < 4; n++) wmma::fill_fragment(fs[n], 0.f);
#pragma unroll
        for (int k = 0; k < 4; k++) {
            wmma::fragment<wmma::matrix_a, 16, 16, 16, bf16, wmma::row_major> fah, fal;
            wmma::load_matrix_sync(fah, Qh + k * 16, SBQ);
            wmma::load_matrix_sync(fal, Ql + k * 16, SBQ);
#pragma unroll
            for (int n = 0; n < 4; n++) {
                wmma::fragment<wmma::matrix_b, 16, 16, 16, bf16, wmma::col_major> fbh, fbl;
                wmma::load_matrix_sync(fbh, Kh + (n * 16) * SBQ + k * 16, SBQ);
                wmma::load_matrix_sync(fbl, Kl + (n * 16) * SBQ + k * 16, SBQ);
                wmma::mma_sync(fs[n], fah, fbh, fs[n]);
                wmma::mma_sync(fs[n], fah, fbl, fs[n]);
                wmma::mma_sync(fs[n], fal, fbh, fs[n]);
            }
        }
#pragma unroll
        for (int n = 0; n < 4; n++)
            wmma::store_matrix_sync(Ssw + n * 16, fs[n], SSW, wmma::mem_row_major);
        __syncwarp();

        // ---- warp-private softmax (no max subtraction; shift-invariant) ----
        {
            const int row = wid * 16 + r16;
            const int q = q0 + row;
            const uint32_t* dmp = dmask + ((size_t)b * T_ + q) * T_ + k0 + hf * 32;
            float rsum = 0.f;
#pragma unroll
            for (int jj = 0; jj < 8; jj++) {
                const uint4 m4 = ((const uint4*)dmp)[jj];
                const int cb = hf * 32 + jj * 4;
                const int kk = k0 + cb;
                const float s0 = Ssw[r16 * SSW + cb + 0];
                const float s1 = Ssw[r16 * SSW + cb + 1];
                const float s2 = Ssw[r16 * SSW + cb + 2];
                const float s3 = Ssw[r16 * SSW + cb + 3];
                const float p0 = ((m4.x != 0u) || causal_masked(q, kk + 0)) ? 0.f : __expf(s0 * 0.125f);
                const float p1 = ((m4.y != 0u) || causal_masked(q, kk + 1)) ? 0.f : __expf(s1 * 0.125f);
                const float p2 = ((m4.z != 0u) || causal_masked(q, kk + 2)) ? 0.f : __expf(s2 * 0.125f);
                const float p3 = ((m4.w != 0u) || causal_masked(q, kk + 3)) ? 0.f : __expf(s3 * 0.125f);
                rsum += (p0 + p1) + (p2 + p3);
                const bf16 h0 = __float2bfloat16_rn(p0);
                const bf16 h1 = __float2bfloat16_rn(p1);
                const bf16 h2 = __float2bfloat16_rn(p2);
                const bf16 h3 = __float2bfloat16_rn(p3);
                *(__nv_bfloat162*)&Ph[r16 * SBQ + cb]     = __nv_bfloat162(h0, h1);
                *(__nv_bfloat162*)&Ph[r16 * SBQ + cb + 2] = __nv_bfloat162(h2, h3);
                *(__nv_bfloat162*)&Pl[r16 * SBQ + cb] =
                    __nv_bfloat162(__float2bfloat16_rn(p0 - __bfloat162float(h0)),
                                   __float2bfloat16_rn(p1 - __bfloat162float(h1)));
                *(__nv_bfloat162*)&Pl[r16 * SBQ + cb + 2] =
                    __nv_bfloat162(__float2bfloat16_rn(p2 - __bfloat162float(h2)),
                                   __float2bfloat16_rn(p3 - __bfloat162float(h3)));
            }
            rsum += __shfl_xor_sync(0xffffffffu, rsum, 1);
            li += rsum;
        }
        __syncwarp();

        // ---- O += P V (split, 3 products) into persistent fragments ----
#pragma unroll
        for (int k = 0; k < 4; k++) {
            wmma::fragment<wmma::matrix_a, 16, 16, 16, bf16, wmma::row_major> fph, fpl;
            wmma::load_matrix_sync(fph, Ph + k * 16, SBQ);
            wmma::load_matrix_sync(fpl, Pl + k * 16, SBQ);
#pragma unroll
            for (int n = 0; n < 4; n++) {
                wmma::fragment<wmma::matrix_b, 16, 16, 16, bf16, wmma::row_major> fvh, fvl;
                wmma::load_matrix_sync(fvh, Vh + (k * 16) * SBQ + n * 16, SBQ);
                wmma::load_matrix_sync(fvl, Vl + (k * 16) * SBQ + n * 16, SBQ);
                wmma::mma_sync(fo[n], fph, fvh, fo[n]);
                wmma::mma_sync(fo[n], fph, fvl, fo[n]);
                wmma::mma_sync(fo[n], fpl, fvh, fo[n]);
            }
        }

        if (s + 1 < nt) {
            asm volatile("cp.async.wait_group 0;" ::: "memory");
            __syncthreads();
        }
    }

    // ---- epilogue: stage O, divide by li (0/0 -> NaN), write bf16 hi/lo ----
#pragma unroll
    for (int n = 0; n < 4; n++)
        wmma::store_matrix_sync(Ssw + n * 16, fo[n], SSW, wmma::mem_row_major);
    __syncwarp();
    {
        const int row = wid * 16 + r16;
        const int q = q0 + row;
        bf16* yhp = yh + ((size_t)b * T_ + q) * C_ + h * 64 + hf * 32;
        bf16* ylp = yl + ((size_t)b * T_ + q) * C_ + h * 64 + hf * 32;
#pragma unroll
        for (int j = 0; j < 32; j++) {
            const float v = Ssw[r16 * SSW + hf * 32 + j] / li;
            const bf16 hh = __float2bfloat16_rn(v);
            yhp[j] = hh;
            ylp[j] = __float2bfloat16_rn(v - __bfloat162float(hh));
        }
    }
}

// ---------------------------------------------------------------------------
extern "C" void kernel_launch(void* const* d_in, const int* in_sizes, int n_in,
                              void* d_out, int out_size)
{
    const float* x  = (const float*)d_in[0];
    const uint32_t* dmask = (const uint32_t*)d_in[1];
    const float* Wq = (const float*)d_in[3];
    const float* bq = (const float*)d_in[4];
    const float* Wk = (const float*)d_in[5];
    const float* bk = (const float*)d_in[6];
    const float* Wv = (const float*)d_in[7];
    const float* bv = (const float*)d_in[8];
    const float* Wo = (const float*)d_in[9];
    const float* bo = (const float*)d_in[10];

    bf16 *ah, *al, *wh, *wl, *yh, *yl;
    cudaGetSymbolAddress((void**)&ah, g_ah);
    cudaGetSymbolAddress((void**)&al, g_al);
    cudaGetSymbolAddress((void**)&wh, g_wh);
    cudaGetSymbolAddress((void**)&wl, g_wl);
    cudaGetSymbolAddress((void**)&yh, g_yh);
    cudaGetSymbolAddress((void**)&yl, g_yl);

    split_kernel<<<(MTOT * C_ / 4 + 255) / 256, 256>>>(x, ah, al, MTOT * C_ / 4);
    const int wn4 = C_ * C_ / 4;
    split_kernel<<<(wn4 + 255) / 256, 256>>>(Wq, wh + 0 * C_ * C_, wl + 0 * C_ * C_, wn4);
    split_kernel<<<(wn4 + 255) / 256, 256>>>(Wk, wh + 1 * C_ * C_, wl + 1 * C_ * C_, wn4);
    split_kernel<<<(wn4 + 255) / 256, 256>>>(Wv, wh + 2 * C_ * C_, wl + 2 * C_ * C_, wn4);
    split_kernel<<<(wn4 + 255) / 256, 256>>>(Wo, wh + 3 * C_ * C_, wl + 3 * C_ * C_, wn4);

    cudaFuncSetAttribute(gemm_wmma<0>, cudaFuncAttributeMaxDynamicSharedMemorySize, GSMEM);
    cudaFuncSetAttribute(gemm_wmma<1>, cudaFuncAttributeMaxDynamicSharedMemorySize, GSMEM);
    cudaFuncSetAttribute(attn_wmma2, cudaFuncAttributeMaxDynamicSharedMemorySize, ASMEM);

    // merged QKV projections (grid.z = 3)
    gemm_wmma<0><<<dim3(C_ / 128, MTOT / 128, 3), 256, GSMEM>>>(
        ah, al, wh, wl, bq, bk, bv, nullptr);

    attn_wmma2<<<dim3(T_ / 128, H_, B_), 256, ASMEM>>>(dmask, yh, yl);

    gemm_wmma<1><<<dim3(C_ / 128, MTOT / 128), 256, GSMEM>>>(
        yh, yl, wh + 3 * C_ * C_, wl + 3 * C_ * C_, bo, nullptr, nullptr, (float*)d_out);
}

// round 7
// speedup vs baseline: 1.7718x; 1.0843x over previous
#include <cuda_runtime.h>
#include <cuda_bf16.h>
#include <mma.h>
#include <math.h>
#include <stdint.h>

using namespace nvcuda;

#define B_ 2
#define T_ 2048
#define C_ 1024
#define H_ 16
#define D_ 64
#define MTOT (B_*T_)          // 4096

typedef __nv_bfloat16 bf16;

// ---------------- scratch (__device__ globals; no allocs allowed) ----------
__device__ bf16 g_qh[B_*H_*T_*D_];
__device__ bf16 g_ql[B_*H_*T_*D_];
__device__ bf16 g_kh[B_*H_*T_*D_];
__device__ bf16 g_kl[B_*H_*T_*D_];
__device__ bf16 g_vh[B_*H_*T_*D_];
__device__ bf16 g_vl[B_*H_*T_*D_];
__device__ bf16 g_ah[MTOT*C_];
__device__ bf16 g_al[MTOT*C_];
__device__ bf16 g_wh[4*C_*C_];
__device__ bf16 g_wl[4*C_*C_];
__device__ bf16 g_yh[MTOT*C_];
__device__ bf16 g_yl[MTOT*C_];

// ---------------- helpers --------------------------------------------------
__device__ __forceinline__ uint32_t smem_u32(const void* p) {
    uint32_t a;
    asm("{ .reg .u64 t; cvta.to.shared.u64 t, %1; cvt.u32.u64 %0, t; }" : "=r"(a) : "l"(p));
    return a;
}
__device__ __forceinline__ void cp_async16(uint32_t dst, const void* src) {
    asm volatile("cp.async.cg.shared.global [%0], [%1], 16;" :: "r"(dst), "l"(src) : "memory");
}
__device__ __forceinline__ void ldmx4(uint32_t* r, uint32_t a) {
    asm volatile("ldmatrix.sync.aligned.m8n8.x4.shared.b16 {%0,%1,%2,%3}, [%4];"
                 : "=r"(r[0]), "=r"(r[1]), "=r"(r[2]), "=r"(r[3]) : "r"(a));
}
__device__ __forceinline__ void ldmx4t(uint32_t* r, uint32_t a) {
    asm volatile("ldmatrix.sync.aligned.m8n8.x4.trans.shared.b16 {%0,%1,%2,%3}, [%4];"
                 : "=r"(r[0]), "=r"(r[1]), "=r"(r[2]), "=r"(r[3]) : "r"(a));
}
__device__ __forceinline__ void mma16816(float* c, const uint32_t* a, const uint32_t* b) {
    asm volatile("mma.sync.aligned.m16n8k16.row.col.f32.bf16.bf16.f32 "
                 "{%0,%1,%2,%3}, {%4,%5,%6,%7}, {%8,%9}, {%0,%1,%2,%3};"
                 : "+f"(c[0]), "+f"(c[1]), "+f"(c[2]), "+f"(c[3])
                 : "r"(a[0]), "r"(a[1]), "r"(a[2]), "r"(a[3]), "r"(b[0]), "r"(b[1]));
}

// ---------------- split fp32 -> bf16 hi/lo ---------------------------------
__global__ void split_kernel(const float* __restrict__ in,
                             bf16* __restrict__ hi, bf16* __restrict__ lo, int n4)
{
    const int i = blockIdx.x * blockDim.x + threadIdx.x;
    if (i >= n4) return;
    float4 v = ((const float4*)in)[i];
    bf16 h0 = __float2bfloat16_rn(v.x);
    bf16 h1 = __float2bfloat16_rn(v.y);
    bf16 h2 = __float2bfloat16_rn(v.z);
    bf16 h3 = __float2bfloat16_rn(v.w);
    bf16 l0 = __float2bfloat16_rn(v.x - __bfloat162float(h0));
    bf16 l1 = __float2bfloat16_rn(v.y - __bfloat162float(h1));
    bf16 l2 = __float2bfloat16_rn(v.z - __bfloat162float(h2));
    bf16 l3 = __float2bfloat16_rn(v.w - __bfloat162float(h3));
    __nv_bfloat162* hp = (__nv_bfloat162*)hi;
    __nv_bfloat162* lp = (__nv_bfloat162*)lo;
    hp[2*i]   = __nv_bfloat162(h0, h1);
    hp[2*i+1] = __nv_bfloat162(h2, h3);
    lp[2*i]   = __nv_bfloat162(l0, l1);
    lp[2*i+1] = __nv_bfloat162(l2, l3);
}

// ---------------- WMMA bf16-split GEMM (unchanged) -------------------------
#define KS 32
#define LDSG 40
#define SLAB_ELEMS (128*LDSG)
#define SLAB_BYTES (SLAB_ELEMS*2)
#define STAGE_BYTES (4*SLAB_BYTES)
#define GSMEM (2*STAGE_BYTES)

template<int MODE>
__global__ __launch_bounds__(256, 1)
void gemm_wmma(const bf16* __restrict__ Ah, const bf16* __restrict__ Al,
               const bf16* __restrict__ WhBase, const bf16* __restrict__ WlBase,
               const float* __restrict__ b0, const float* __restrict__ b1,
               const float* __restrict__ b2, float* __restrict__ out_f)
{
    extern __shared__ char dynsmem[];
    bf16* stage = (bf16*)dynsmem;
    float* osm = (float*)dynsmem;
    const uint32_t sb = smem_u32(dynsmem);

    const int z = (MODE == 0) ? (int)blockIdx.z : 0;
    const bf16* Bh = WhBase + (size_t)z * C_ * C_;
    const bf16* Bl = WlBase + (size_t)z * C_ * C_;
    const float* bias = (z == 0) ? b0 : (z == 1) ? b1 : b2;
    bf16* outh = (MODE == 0) ? ((z == 0) ? g_qh : (z == 1) ? g_kh : g_vh) : nullptr;
    bf16* outl = (MODE == 0) ? ((z == 0) ? g_ql : (z == 1) ? g_kl : g_vl) : nullptr;

    const int tid = threadIdx.x;
    const int wid = tid >> 5;
    const int n0 = blockIdx.x * 128;
    const int m0 = blockIdx.y * 128;
    const int warp_m = wid >> 1;
    const int warp_n = wid & 1;

    auto issue = [&](int s, int b) {
        const int c0 = s * KS;
#pragma unroll
        for (int i = 0; i < 8; i++) {
            const int arr = i >> 1;
            const int rem = ((i & 1) << 8) + tid;
            const int r = rem >> 2;
            const int ch = rem & 3;
            const bf16* g = (arr == 0) ? Ah : (arr == 1) ? Al : (arr == 2) ? Bh : Bl;
            const int row = ((arr < 2) ? m0 : n0) + r;
            cp_async16(sb + b * STAGE_BYTES + arr * SLAB_BYTES + r * (LDSG * 2) + ch * 16,
                       g + (size_t)row * 1024 + c0 + ch * 8);
        }
        asm volatile("cp.async.commit_group;" ::: "memory");
    };

    wmma::fragment<wmma::accumulator, 16, 16, 16, float> fc[2][4];
#pragma unroll
    for (int i = 0; i < 2; i++)
#pragma unroll
        for (int j = 0; j < 4; j++) wmma::fill_fragment(fc[i][j], 0.f);

    issue(0, 0);

    const int NS = 1024 / KS;
    for (int s = 0; s < NS; s++) {
        const int buf = s & 1;
        if (s + 1 < NS) {
            issue(s + 1, buf ^ 1);
            asm volatile("cp.async.wait_group 1;" ::: "memory");
        } else {
            asm volatile("cp.async.wait_group 0;" ::: "memory");
        }
        __syncthreads();

        const bf16* Ah_s = stage + buf * (4 * SLAB_ELEMS);
        const bf16* Al_s = Ah_s + SLAB_ELEMS;
        const bf16* Bh_s = Al_s + SLAB_ELEMS;
        const bf16* Bl_s = Bh_s + SLAB_ELEMS;

#pragma unroll
        for (int ks = 0; ks < KS; ks += 16) {
            wmma::fragment<wmma::matrix_a, 16, 16, 16, bf16, wmma::row_major> fah[2], fal[2];
            wmma::fragment<wmma::matrix_b, 16, 16, 16, bf16, wmma::col_major> fbh[4], fbl[4];
#pragma unroll
            for (int i = 0; i < 2; i++) {
                wmma::load_matrix_sync(fah[i], Ah_s + (warp_m * 32 + 16 * i) * LDSG + ks, LDSG);
                wmma::load_matrix_sync(fal[i], Al_s + (warp_m * 32 + 16 * i) * LDSG + ks, LDSG);
            }
#pragma unroll
            for (int j = 0; j < 4; j++) {
                wmma::load_matrix_sync(fbh[j], Bh_s + (warp_n * 64 + 16 * j) * LDSG + ks, LDSG);
                wmma::load_matrix_sync(fbl[j], Bl_s + (warp_n * 64 + 16 * j) * LDSG + ks, LDSG);
            }
#pragma unroll
            for (int i = 0; i < 2; i++)
#pragma unroll
                for (int j = 0; j < 4; j++) {
                    wmma::mma_sync(fc[i][j], fah[i], fbh[j], fc[i][j]);
                    wmma::mma_sync(fc[i][j], fah[i], fbl[j], fc[i][j]);
                    wmma::mma_sync(fc[i][j], fal[i], fbh[j], fc[i][j]);
                }
        }
        __syncthreads();
    }

#pragma unroll
    for (int i = 0; i < 2; i++)
#pragma unroll
        for (int j = 0; j < 4; j++)
            wmma::store_matrix_sync(osm + (warp_m * 32 + 16 * i) * 128 + warp_n * 64 + 16 * j,
                                    fc[i][j], 128, wmma::mem_row_major);
    __syncthreads();

    for (int idx4 = tid; idx4 < 128 * 32; idx4 += 256) {
        const int r = idx4 >> 5;
        const int c = (idx4 & 31) << 2;
        float4 v = *(float4*)&osm[r * 128 + c];
        const int n = n0 + c;
        v.x += bias[n + 0]; v.y += bias[n + 1]; v.z += bias[n + 2]; v.w += bias[n + 3];
        const int m = m0 + r;
        if (MODE == 0) {
            const int bb = m >> 11, tt = m & (T_ - 1);
            const int hh = n >> 6,  dd = n & 63;
            const size_t off = (((size_t)bb * H_ + hh) * T_ + tt) * D_ + dd;
            bf16 h0 = __float2bfloat16_rn(v.x), h1 = __float2bfloat16_rn(v.y);
            bf16 h2 = __float2bfloat16_rn(v.z), h3 = __float2bfloat16_rn(v.w);
            bf16 l0 = __float2bfloat16_rn(v.x - __bfloat162float(h0));
            bf16 l1 = __float2bfloat16_rn(v.y - __bfloat162float(h1));
            bf16 l2 = __float2bfloat16_rn(v.z - __bfloat162float(h2));
            bf16 l3 = __float2bfloat16_rn(v.w - __bfloat162float(h3));
            *(__nv_bfloat162*)(outh + off)     = __nv_bfloat162(h0, h1);
            *(__nv_bfloat162*)(outh + off + 2) = __nv_bfloat162(h2, h3);
            *(__nv_bfloat162*)(outl + off)     = __nv_bfloat162(l0, l1);
            *(__nv_bfloat162*)(outl + off + 2) = __nv_bfloat162(l2, l3);
        } else {
            *(float4*)(out_f + (size_t)m * C_ + n) = v;
        }
    }
}

// ---------------- analytic causal/step mask --------------------------------
__device__ __forceinline__ bool causal_masked(int q, int k) {
    const bool step = (q >> 5) == (k >> 5);
    const bool tri  = (k <= q) && ((q & 3) != 3) && ((k & 3) != 3);
    return !(step || tri);
}

// ---------------- register-resident flash attention ------------------------
// 128 Q rows/block, 8 warps x 16 rows. S and P never touch smem: mma.m16n8k16
// accumulator layout == A-fragment layout, so mask/exp/split happen in regs.
#define SBQB 144            // bf16 row stride in bytes (64 d + 8 pad)
#define AQH_OFF 0           // Q hi: 128 x 144
#define AQL_OFF 18432
#define AKV_OFF 36864       // per buf: Kh,Kl,Vh,Vl each 64*144 = 9216
#define AKVBUF  36864
#define ASMEM   110592

__global__ __launch_bounds__(256)
void attn_reg(const uint32_t* __restrict__ dmask,
              bf16* __restrict__ yh, bf16* __restrict__ yl)
{
    extern __shared__ char dyn[];
    const uint32_t sb = smem_u32(dyn);
    const int b = blockIdx.z, h = blockIdx.y;
    const int qi = (int)gridDim.x - 1 - (int)blockIdx.x;   // heavy first
    const int q0 = qi * 128;
    const int tid = threadIdx.x, wid = tid >> 5, lane = tid & 31;
    const int g = lane >> 2, t2 = (lane & 3) * 2;
    const int lm = lane >> 3, lr = lane & 7;               // ldmatrix addressing
    const size_t headoff = ((size_t)b * H_ + h) * T_;

    // ---- stage Q (hi/lo) ----
    {
        const bf16* qhg = g_qh + (headoff + q0) * D_;
        const bf16* qlg = g_ql + (headoff + q0) * D_;
#pragma unroll
        for (int i = 0; i < 8; i++) {
            const int c = tid + i * 256;
            const int arr = c >> 10;
            const int rem = c & 1023;
            const int r = rem >> 3, ch = rem & 7;
            const bf16* gp = arr ? qlg : qhg;
            cp_async16(sb + (arr ? AQL_OFF : AQH_OFF) + r * SBQB + ch * 16,
                       gp + (size_t)r * D_ + ch * 8);
        }
    }

    auto issueKV = [&](int kt, int buf) {
        const int k0 = kt * 64;
#pragma unroll
        for (int i = 0; i < 8; i++) {
            const int c = tid + i * 256;
            const int arr = c >> 9;
            const int rem = c & 511;
            const int r = rem >> 3, ch = rem & 7;
            const bf16* gp = (arr == 0) ? g_kh : (arr == 1) ? g_kl : (arr == 2) ? g_vh : g_vl;
            cp_async16(sb + AKV_OFF + buf * AKVBUF + arr * 9216 + r * SBQB + ch * 16,
                       gp + (headoff + k0 + r) * D_ + ch * 8);
        }
        asm volatile("cp.async.commit_group;" ::: "memory");
    };

    issueKV(0, 0);   // commits Q loads too
    asm volatile("cp.async.wait_group 0;" ::: "memory");
    __syncthreads();

    // ---- Q fragments into registers (once) ----
    uint32_t qfh[4][4], qfl[4][4];
#pragma unroll
    for (int kt = 0; kt < 4; kt++) {
        const uint32_t a = sb + AQH_OFF + (wid * 16 + (lm & 1) * 8 + lr) * SBQB
                         + kt * 32 + (lm >> 1) * 16;
        ldmx4(qfh[kt], a);
        ldmx4(qfl[kt], a + (AQL_OFF - AQH_OFF));
    }

    float fo[8][4];
#pragma unroll
    for (int j = 0; j < 8; j++)
#pragma unroll
        for (int e = 0; e < 4; e++) fo[j][e] = 0.f;
    float li0 = 0.f, li1 = 0.f;

    const int qr0 = q0 + wid * 16 + g, qr1 = qr0 + 8;
    const uint32_t* dm0 = dmask + ((size_t)b * T_ + qr0) * T_;
    const uint32_t* dm1 = dmask + ((size_t)b * T_ + qr1) * T_;

    const int nt = 2 * qi + 2;
    for (int s = 0; s < nt; s++) {
        const int buf = s & 1;
        if (s + 1 < nt) issueKV(s + 1, buf ^ 1);
        const uint32_t kb = sb + AKV_OFF + buf * AKVBUF;
        const int k0 = s * 64;

        // ---- S = Q K^T : 16x64 in registers ----
        float fs[8][4];
#pragma unroll
        for (int j = 0; j < 8; j++)
#pragma unroll
            for (int e = 0; e < 4; e++) fs[j][e] = 0.f;
#pragma unroll
        for (int kt = 0; kt < 4; kt++) {
#pragma unroll
            for (int jp = 0; jp < 4; jp++) {
                uint32_t kh[4], kl[4];
                const uint32_t ka = kb + (jp * 16 + (lm >> 1) * 8 + lr) * SBQB
                                  + kt * 32 + (lm & 1) * 16;
                ldmx4(kh, ka);
                ldmx4(kl, ka + 9216);
                mma16816(fs[2*jp],   qfh[kt], kh);
                mma16816(fs[2*jp],   qfh[kt], kl);
                mma16816(fs[2*jp],   qfl[kt], kh);
                mma16816(fs[2*jp+1], qfh[kt], kh + 2);
                mma16816(fs[2*jp+1], qfh[kt], kl + 2);
                mma16816(fs[2*jp+1], qfl[kt], kh + 2);
            }
        }

        // ---- mask + exp + bf16-split, all in registers ----
        uint32_t ph[4][4], pl[4][4];
#pragma unroll
        for (int j = 0; j < 8; j++) {
            const int col = k0 + j * 8 + t2;
            const uint2 ma = *(const uint2*)(dm0 + col);
            const uint2 mb = *(const uint2*)(dm1 + col);
            const float p0 = (ma.x || causal_masked(qr0, col))     ? 0.f : __expf(fs[j][0] * 0.125f);
            const float p1 = (ma.y || causal_masked(qr0, col + 1)) ? 0.f : __expf(fs[j][1] * 0.125f);
            const float p2 = (mb.x || causal_masked(qr1, col))     ? 0.f : __expf(fs[j][2] * 0.125f);
            const float p3 = (mb.y || causal_masked(qr1, col + 1)) ? 0.f : __expf(fs[j][3] * 0.125f);
            li0 += p0 + p1;
            li1 += p2 + p3;
            const bf16 h0 = __float2bfloat16_rn(p0), h1 = __float2bfloat16_rn(p1);
            const bf16 h2 = __float2bfloat16_rn(p2), h3 = __float2bfloat16_rn(p3);
            __nv_bfloat162 H01(h0, h1), H23(h2, h3);
            __nv_bfloat162 L01(__float2bfloat16_rn(p0 - __bfloat162float(h0)),
                               __float2bfloat16_rn(p1 - __bfloat162float(h1)));
            __nv_bfloat162 L23(__float2bfloat16_rn(p2 - __bfloat162float(h2)),
                               __float2bfloat16_rn(p3 - __bfloat162float(h3)));
            const int kt = j >> 1, hk = (j & 1) * 2;
            ph[kt][hk + 0] = *(uint32_t*)&H01;
            ph[kt][hk + 1] = *(uint32_t*)&H23;
            pl[kt][hk + 0] = *(uint32_t*)&L01;
            pl[kt][hk + 1] = *(uint32_t*)&L23;
        }
        // NOTE: A-frag order is {row g k-lo, row g+8 k-lo, row g k-hi, row g+8 k-hi}
        // j even (k-lo) -> regs 0,1 ; j odd (k-hi) -> regs 2,3.  hk above does this.

        // ---- O += P V : persistent register accumulators ----
#pragma unroll
        for (int kt = 0; kt < 4; kt++) {
#pragma unroll
            for (int jp = 0; jp < 4; jp++) {
                uint32_t vh[4], vl[4];
                const uint32_t va = kb + 18432 + (kt * 16 + (lm & 1) * 8 + lr) * SBQB
                                  + jp * 32 + (lm >> 1) * 16;
                ldmx4t(vh, va);
                ldmx4t(vl, va + 9216);
                mma16816(fo[2*jp],   ph[kt], vh);
                mma16816(fo[2*jp],   ph[kt], vl);
                mma16816(fo[2*jp],   pl[kt], vh);
                mma16816(fo[2*jp+1], ph[kt], vh + 2);
                mma16816(fo[2*jp+1], ph[kt], vl + 2);
                mma16816(fo[2*jp+1], pl[kt], vh + 2);
            }
        }

        if (s + 1 < nt) {
            asm volatile("cp.async.wait_group 0;" ::: "memory");
            __syncthreads();
        }
    }

    // ---- epilogue: quad-reduce li, divide (0/0 -> NaN), write bf16 hi/lo ----
    li0 += __shfl_xor_sync(0xffffffffu, li0, 1);
    li0 += __shfl_xor_sync(0xffffffffu, li0, 2);
    li1 += __shfl_xor_sync(0xffffffffu, li1, 1);
    li1 += __shfl_xor_sync(0xffffffffu, li1, 2);

    bf16* yh0 = yh + ((size_t)b * T_ + qr0) * C_ + h * 64;
    bf16* yl0 = yl + ((size_t)b * T_ + qr0) * C_ + h * 64;
    bf16* yh1 = yh + ((size_t)b * T_ + qr1) * C_ + h * 64;
    bf16* yl1 = yl + ((size_t)b * T_ + qr1) * C_ + h * 64;
#pragma unroll
    for (int j = 0; j < 8; j++) {
        const int col = j * 8 + t2;
        const float v0 = fo[j][0] / li0, v1 = fo[j][1] / li0;
        const float v2 = fo[j][2] / li1, v3 = fo[j][3] / li1;
        const bf16 h0 = __float2bfloat16_rn(v0), h1 = __float2bfloat16_rn(v1);
        const bf16 h2 = __float2bfloat16_rn(v2), h3 = __float2bfloat16_rn(v3);
        *(__nv_bfloat162*)(yh0 + col) = __nv_bfloat162(h0, h1);
        *(__nv_bfloat162*)(yl0 + col) =
            __nv_bfloat162(__float2bfloat16_rn(v0 - __bfloat162float(h0)),
                           __float2bfloat16_rn(v1 - __bfloat162float(h1)));
        *(__nv_bfloat162*)(yh1 + col) = __nv_bfloat162(h2, h3);
        *(__nv_bfloat162*)(yl1 + col) =
            __nv_bfloat162(__float2bfloat16_rn(v2 - __bfloat162float(h2)),
                           __float2bfloat16_rn(v3 - __bfloat162float(h3)));
    }
}

// ---------------------------------------------------------------------------
extern "C" void kernel_launch(void* const* d_in, const int* in_sizes, int n_in,
                              void* d_out, int out_size)
{
    const float* x  = (const float*)d_in[0];
    const uint32_t* dmask = (const uint32_t*)d_in[1];
    const float* Wq = (const float*)d_in[3];
    const float* bq = (const float*)d_in[4];
    const float* Wk = (const float*)d_in[5];
    const float* bk = (const float*)d_in[6];
    const float* Wv = (const float*)d_in[7];
    const float* bv = (const float*)d_in[8];
    const float* Wo = (const float*)d_in[9];
    const float* bo = (const float*)d_in[10];

    bf16 *ah, *al, *wh, *wl, *yh, *yl;
    cudaGetSymbolAddress((void**)&ah, g_ah);
    cudaGetSymbolAddress((void**)&al, g_al);
    cudaGetSymbolAddress((void**)&wh, g_wh);
    cudaGetSymbolAddress((void**)&wl, g_wl);
    cudaGetSymbolAddress((void**)&yh, g_yh);
    cudaGetSymbolAddress((void**)&yl, g_yl);

    split_kernel<<<(MTOT * C_ / 4 + 255) / 256, 256>>>(x, ah, al, MTOT * C_ / 4);
    const int wn4 = C_ * C_ / 4;
    split_kernel<<<(wn4 + 255) / 256, 256>>>(Wq, wh + 0 * C_ * C_, wl + 0 * C_ * C_, wn4);
    split_kernel<<<(wn4 + 255) / 256, 256>>>(Wk, wh + 1 * C_ * C_, wl + 1 * C_ * C_, wn4);
    split_kernel<<<(wn4 + 255) / 256, 256>>>(Wv, wh + 2 * C_ * C_, wl + 2 * C_ * C_, wn4);
    split_kernel<<<(wn4 + 255) / 256, 256>>>(Wo, wh + 3 * C_ * C_, wl + 3 * C_ * C_, wn4);

    cudaFuncSetAttribute(gemm_wmma<0>, cudaFuncAttributeMaxDynamicSharedMemorySize, GSMEM);
    cudaFuncSetAttribute(gemm_wmma<1>, cudaFuncAttributeMaxDynamicSharedMemorySize, GSMEM);
    cudaFuncSetAttribute(attn_reg, cudaFuncAttributeMaxDynamicSharedMemorySize, ASMEM);

    gemm_wmma<0><<<dim3(C_ / 128, MTOT / 128, 3), 256, GSMEM>>>(
        ah, al, wh, wl, bq, bk, bv, nullptr);

    attn_reg<<<dim3(T_ / 128, H_, B_), 256, ASMEM>>>(dmask, yh, yl);

    gemm_wmma<1><<<dim3(C_ / 128, MTOT / 128), 256, GSMEM>>>(
        yh, yl, wh + 3 * C_ * C_, wl + 3 * C_ * C_, bo, nullptr, nullptr, (float*)d_out);
}

// round 9
// speedup vs baseline: 2.1033x; 1.1871x over previous
#include <cuda_runtime.h>
#include <cuda_bf16.h>
#include <math.h>
#include <stdint.h>

#define B_ 2
#define T_ 2048
#define C_ 1024
#define H_ 16
#define D_ 64
#define MTOT (B_*T_)          // 4096

typedef __nv_bfloat16 bf16;

// ---------------- scratch (__device__ globals; no allocs allowed) ----------
__device__ bf16 g_qh[B_*H_*T_*D_];
__device__ bf16 g_ql[B_*H_*T_*D_];
__device__ bf16 g_kh[B_*H_*T_*D_];
__device__ bf16 g_kl[B_*H_*T_*D_];
__device__ bf16 g_vh[B_*H_*T_*D_];
__device__ bf16 g_vl[B_*H_*T_*D_];
__device__ bf16 g_ah[MTOT*C_];
__device__ bf16 g_al[MTOT*C_];
__device__ bf16 g_wh[4*C_*C_];
__device__ bf16 g_wl[4*C_*C_];
__device__ bf16 g_yh[MTOT*C_];
__device__ bf16 g_yl[MTOT*C_];

// ---------------- helpers --------------------------------------------------
__device__ __forceinline__ uint32_t smem_u32(const void* p) {
    uint32_t a;
    asm("{ .reg .u64 t; cvta.to.shared.u64 t, %1; cvt.u32.u64 %0, t; }" : "=r"(a) : "l"(p));
    return a;
}
__device__ __forceinline__ void cp_async16(uint32_t dst, const void* src) {
    asm volatile("cp.async.cg.shared.global [%0], [%1], 16;" :: "r"(dst), "l"(src) : "memory");
}
__device__ __forceinline__ void ldmx4(uint32_t* r, uint32_t a) {
    asm volatile("ldmatrix.sync.aligned.m8n8.x4.shared.b16 {%0,%1,%2,%3}, [%4];"
                 : "=r"(r[0]), "=r"(r[1]), "=r"(r[2]), "=r"(r[3]) : "r"(a));
}
__device__ __forceinline__ void ldmx4t(uint32_t* r, uint32_t a) {
    asm volatile("ldmatrix.sync.aligned.m8n8.x4.trans.shared.b16 {%0,%1,%2,%3}, [%4];"
                 : "=r"(r[0]), "=r"(r[1]), "=r"(r[2]), "=r"(r[3]) : "r"(a));
}
__device__ __forceinline__ void mma16816(float* c, const uint32_t* a, const uint32_t* b) {
    asm volatile("mma.sync.aligned.m16n8k16.row.col.f32.bf16.bf16.f32 "
                 "{%0,%1,%2,%3}, {%4,%5,%6,%7}, {%8,%9}, {%0,%1,%2,%3};"
                 : "+f"(c[0]), "+f"(c[1]), "+f"(c[2]), "+f"(c[3])
                 : "r"(a[0]), "r"(a[1]), "r"(a[2]), "r"(a[3]), "r"(b[0]), "r"(b[1]));
}

// ---------------- split fp32 -> bf16 hi/lo ---------------------------------
__device__ __forceinline__ void split_body(const float* __restrict__ in,
                                           bf16* __restrict__ hi, bf16* __restrict__ lo, int i)
{
    float4 v = ((const float4*)in)[i];
    bf16 h0 = __float2bfloat16_rn(v.x);
    bf16 h1 = __float2bfloat16_rn(v.y);
    bf16 h2 = __float2bfloat16_rn(v.z);
    bf16 h3 = __float2bfloat16_rn(v.w);
    bf16 l0 = __float2bfloat16_rn(v.x - __bfloat162float(h0));
    bf16 l1 = __float2bfloat16_rn(v.y - __bfloat162float(h1));
    bf16 l2 = __float2bfloat16_rn(v.z - __bfloat162float(h2));
    bf16 l3 = __float2bfloat16_rn(v.w - __bfloat162float(h3));
    __nv_bfloat162* hp = (__nv_bfloat162*)hi;
    __nv_bfloat162* lp = (__nv_bfloat162*)lo;
    hp[2*i]   = __nv_bfloat162(h0, h1);
    hp[2*i+1] = __nv_bfloat162(h2, h3);
    lp[2*i]   = __nv_bfloat162(l0, l1);
    lp[2*i+1] = __nv_bfloat162(l2, l3);
}
__global__ void split_kernel(const float* __restrict__ in,
                             bf16* __restrict__ hi, bf16* __restrict__ lo, int n4)
{
    const int i = blockIdx.x * blockDim.x + threadIdx.x;
    if (i < n4) split_body(in, hi, lo, i);
}
__global__ void split4_kernel(const float* __restrict__ w0, const float* __restrict__ w1,
                              const float* __restrict__ w2, const float* __restrict__ w3,
                              bf16* __restrict__ hi, bf16* __restrict__ lo, int n4)
{
    const int z = blockIdx.y;
    const float* src = (z == 0) ? w0 : (z == 1) ? w1 : (z == 2) ? w2 : w3;
    const int i = blockIdx.x * blockDim.x + threadIdx.x;
    if (i < n4) split_body(src, hi + (size_t)z * C_ * C_, lo + (size_t)z * C_ * C_, i);
}

// ---------------- raw-mma bf16-split GEMM ----------------------------------
// out[m,n] = sum_k A[m,k]*W[n,k] + bias[n]; 3 split products on tensor cores.
// 128 threads, 4 warps of 64x64; K-slab 32; 3-stage swizzled smem pipeline.
// MODE 0: grid.z selects Wq/Wk/Wv, writes bf16 hi/lo scattered to (B,H,T,D).
// MODE 1: fp32 row-major output.
#define GARR 8192            // one operand array: 128 rows x 64B
#define GSTAGE 32768         // Ah,Al,Bh,Bl
#define GSMEM2 (3*GSTAGE)    // 98304

template<int MODE>
__global__ __launch_bounds__(128, 2)
void gemm_mma(const bf16* __restrict__ Ah, const bf16* __restrict__ Al,
              const bf16* __restrict__ WhBase, const bf16* __restrict__ WlBase,
              const float* __restrict__ b0, const float* __restrict__ b1,
              const float* __restrict__ b2, float* __restrict__ out_f)
{
    extern __shared__ char dynsmem[];
    const uint32_t sb = smem_u32(dynsmem);

    const int z = (MODE == 0) ? (int)blockIdx.z : 0;
    const bf16* Bh = WhBase + (size_t)z * C_ * C_;
    const bf16* Bl = WlBase + (size_t)z * C_ * C_;
    const float* bias = (z == 0) ? b0 : (z == 1) ? b1 : b2;
    bf16* outh = (MODE == 0) ? ((z == 0) ? g_qh : (z == 1) ? g_kh : g_vh) : nullptr;
    bf16* outl = (MODE == 0) ? ((z == 0) ? g_ql : (z == 1) ? g_kl : g_vl) : nullptr;

    const int tid = threadIdx.x, wid = tid >> 5, lane = tid & 31;
    const int warp_m = wid >> 1, warp_n = wid & 1;
    const int g = lane >> 2, t2 = (lane & 3) * 2;
    const int lm = lane >> 3, lr = lane & 7;
    const int n0 = blockIdx.x * 128, m0 = blockIdx.y * 128;

    auto issue = [&](int s, int st) {
        const int c0 = s * 32;
#pragma unroll
        for (int i = 0; i < 16; i++) {
            const int idx = i * 128 + tid;
            const int arr = idx >> 9, rem = idx & 511;
            const int r = rem >> 2, c = rem & 3;
            const bf16* gp = (arr == 0) ? Ah : (arr == 1) ? Al : (arr == 2) ? Bh : Bl;
            const int row = ((arr < 2) ? m0 : n0) + r;
            cp_async16(sb + st * GSTAGE + arr * GARR + r * 64 + ((c ^ (r & 3)) * 16),
                       gp + (size_t)row * 1024 + c0 + c * 8);
        }
        asm volatile("cp.async.commit_group;" ::: "memory");
    };

    float fc[4][8][4];
#pragma unroll
    for (int im = 0; im < 4; im++)
#pragma unroll
        for (int j = 0; j < 8; j++)
#pragma unroll
            for (int e = 0; e < 4; e++) fc[im][j][e] = 0.f;

    issue(0, 0); issue(1, 1); issue(2, 2);

    for (int s = 0; s < 32; s++) {
        if (s < 30) { asm volatile("cp.async.wait_group 2;" ::: "memory"); }
        else        { asm volatile("cp.async.wait_group 0;" ::: "memory"); }
        __syncthreads();

        const uint32_t stb = sb + (s % 3) * GSTAGE;
#pragma unroll
        for (int kt = 0; kt < 2; kt++) {
            uint32_t bh4[4][4], bl4[4][4];
#pragma unroll
            for (int jp = 0; jp < 4; jp++) {
                const int row = warp_n * 64 + jp * 16 + (lm >> 1) * 8 + lr;
                const int c = kt * 2 + (lm & 1);
                const uint32_t a = stb + 2 * GARR + row * 64 + ((c ^ (row & 3)) * 16);
                ldmx4(bh4[jp], a);
                ldmx4(bl4[jp], a + GARR);
            }
#pragma unroll
            for (int im = 0; im < 4; im++) {
                const int row = warp_m * 64 + im * 16 + (lm & 1) * 8 + lr;
                const int c = kt * 2 + (lm >> 1);
                const uint32_t a = stb + row * 64 + ((c ^ (row & 3)) * 16);
                uint32_t ahf[4], alf[4];
                ldmx4(ahf, a);
                ldmx4(alf, a + GARR);
#pragma unroll
                for (int jp = 0; jp < 4; jp++) {
                    mma16816(fc[im][2*jp],   ahf, bh4[jp]);
                    mma16816(fc[im][2*jp],   ahf, bl4[jp]);
                    mma16816(fc[im][2*jp],   alf, bh4[jp]);
                    mma16816(fc[im][2*jp+1], ahf, bh4[jp] + 2);
                    mma16816(fc[im][2*jp+1], ahf, bl4[jp] + 2);
                    mma16816(fc[im][2*jp+1], alf, bh4[jp] + 2);
                }
            }
        }
        __syncthreads();
        if (s + 3 < 32) issue(s + 3, (s + 3) % 3);
    }

    // ---- epilogue: registers -> global (bias; bf16 hi/lo or fp32) ----
#pragma unroll
    for (int jp = 0; jp < 4; jp++)
#pragma unroll
        for (int n8 = 0; n8 < 2; n8++) {
            const int col = n0 + warp_n * 64 + jp * 16 + n8 * 8 + t2;
            const float bx = __ldg(&bias[col]), by = __ldg(&bias[col + 1]);
#pragma unroll
            for (int im = 0; im < 4; im++) {
                const float* cc = fc[im][2 * jp + n8];
                const int r0 = m0 + warp_m * 64 + im * 16 + g;
                const float v0 = cc[0] + bx, v1 = cc[1] + by;
                const float v2 = cc[2] + bx, v3 = cc[3] + by;
                if (MODE == 0) {
                    const int hh = col >> 6, dd = col & 63;
                    const int bb0 = r0 >> 11, tt0 = r0 & (T_ - 1);
                    const size_t o0 = (((size_t)bb0 * H_ + hh) * T_ + tt0) * D_ + dd;
                    const int r1 = r0 + 8;
                    const int bb1 = r1 >> 11, tt1 = r1 & (T_ - 1);
                    const size_t o1 = (((size_t)bb1 * H_ + hh) * T_ + tt1) * D_ + dd;
                    const bf16 h0 = __float2bfloat16_rn(v0), h1 = __float2bfloat16_rn(v1);
                    const bf16 h2 = __float2bfloat16_rn(v2), h3 = __float2bfloat16_rn(v3);
                    *(__nv_bfloat162*)(outh + o0) = __nv_bfloat162(h0, h1);
                    *(__nv_bfloat162*)(outl + o0) =
                        __nv_bfloat162(__float2bfloat16_rn(v0 - __bfloat162float(h0)),
                                       __float2bfloat16_rn(v1 - __bfloat162float(h1)));
                    *(__nv_bfloat162*)(outh + o1) = __nv_bfloat162(h2, h3);
                    *(__nv_bfloat162*)(outl + o1) =
                        __nv_bfloat162(__float2bfloat16_rn(v2 - __bfloat162float(h2)),
                                       __float2bfloat16_rn(v3 - __bfloat162float(h3)));
                } else {
                    *(float2*)(out_f + (size_t)r0 * C_ + col) = make_float2(v0, v1);
                    *(float2*)(out_f + (size_t)(r0 + 8) * C_ + col) = make_float2(v2, v3);
                }
            }
        }
}

// ---------------- analytic causal/step mask --------------------------------
__device__ __forceinline__ bool causal_masked(int q, int k) {
    const bool step = (q >> 5) == (k >> 5);
    const bool tri  = (k <= q) && ((q & 3) != 3) && ((k & 3) != 3);
    return !(step || tri);
}

// ---------------- register-resident flash attention (unchanged) ------------
#define SBQB 144
#define AQH_OFF 0
#define AQL_OFF 18432
#define AKV_OFF 36864
#define AKVBUF  36864
#define ASMEM   110592

__global__ __launch_bounds__(256)
void attn_reg(const uint32_t* __restrict__ dmask,
              bf16* __restrict__ yh, bf16* __restrict__ yl)
{
    extern __shared__ char dyn[];
    const uint32_t sb = smem_u32(dyn);
    const int b = blockIdx.z, h = blockIdx.y;
    const int qi = (int)gridDim.x - 1 - (int)blockIdx.x;
    const int q0 = qi * 128;
    const int tid = threadIdx.x, wid = tid >> 5, lane = tid & 31;
    const int g = lane >> 2, t2 = (lane & 3) * 2;
    const int lm = lane >> 3, lr = lane & 7;
    const size_t headoff = ((size_t)b * H_ + h) * T_;

    {
        const bf16* qhg = g_qh + (headoff + q0) * D_;
        const bf16* qlg = g_ql + (headoff + q0) * D_;
#pragma unroll
        for (int i = 0; i < 8; i++) {
            const int c = tid + i * 256;
            const int arr = c >> 10;
            const int rem = c & 1023;
            const int r = rem >> 3, ch = rem & 7;
            const bf16* gp = arr ? qlg : qhg;
            cp_async16(sb + (arr ? AQL_OFF : AQH_OFF) + r * SBQB + ch * 16,
                       gp + (size_t)r * D_ + ch * 8);
        }
    }

    auto issueKV = [&](int kt, int buf) {
        const int k0 = kt * 64;
#pragma unroll
        for (int i = 0; i < 8; i++) {
            const int c = tid + i * 256;
            const int arr = c >> 9;
            const int rem = c & 511;
            const int r = rem >> 3, ch = rem & 7;
            const bf16* gp = (arr == 0) ? g_kh : (arr == 1) ? g_kl : (arr == 2) ? g_vh : g_vl;
            cp_async16(sb + AKV_OFF + buf * AKVBUF + arr * 9216 + r * SBQB + ch * 16,
                       gp + (headoff + k0 + r) * D_ + ch * 8);
        }
        asm volatile("cp.async.commit_group;" ::: "memory");
    };

    issueKV(0, 0);
    asm volatile("cp.async.wait_group 0;" ::: "memory");
    __syncthreads();

    uint32_t qfh[4][4], qfl[4][4];
#pragma unroll
    for (int kt = 0; kt < 4; kt++) {
        const uint32_t a = sb + AQH_OFF + (wid * 16 + (lm & 1) * 8 + lr) * SBQB
                         + kt * 32 + (lm >> 1) * 16;
        ldmx4(qfh[kt], a);
        ldmx4(qfl[kt], a + (AQL_OFF - AQH_OFF));
    }

    float fo[8][4];
#pragma unroll
    for (int j = 0; j < 8; j++)
#pragma unroll
        for (int e = 0; e < 4; e++) fo[j][e] = 0.f;
    float li0 = 0.f, li1 = 0.f;

    const int qr0 = q0 + wid * 16 + g, qr1 = qr0 + 8;
    const uint32_t* dm0 = dmask + ((size_t)b * T_ + qr0) * T_;
    const uint32_t* dm1 = dmask + ((size_t)b * T_ + qr1) * T_;

    const int nt = 2 * qi + 2;
    for (int s = 0; s < nt; s++) {
        const int buf = s & 1;
        if (s + 1 < nt) issueKV(s + 1, buf ^ 1);
        const uint32_t kb = sb + AKV_OFF + buf * AKVBUF;
        const int k0 = s * 64;

        float fs[8][4];
#pragma unroll
        for (int j = 0; j < 8; j++)
#pragma unroll
            for (int e = 0; e < 4; e++) fs[j][e] = 0.f;
#pragma unroll
        for (int kt = 0; kt < 4; kt++) {
#pragma unroll
            for (int jp = 0; jp < 4; jp++) {
                uint32_t kh[4], kl[4];
                const uint32_t ka = kb + (jp * 16 + (lm >> 1) * 8 + lr) * SBQB
                                  + kt * 32 + (lm & 1) * 16;
                ldmx4(kh, ka);
                ldmx4(kl, ka + 9216);
                mma16816(fs[2*jp],   qfh[kt], kh);
                mma16816(fs[2*jp],   qfh[kt], kl);
                mma16816(fs[2*jp],   qfl[kt], kh);
                mma16816(fs[2*jp+1], qfh[kt], kh + 2);
                mma16816(fs[2*jp+1], qfh[kt], kl + 2);
                mma16816(fs[2*jp+1], qfl[kt], kh + 2);
            }
        }

        uint32_t ph[4][4], pl[4][4];
#pragma unroll
        for (int j = 0; j < 8; j++) {
            const int col = k0 + j * 8 + t2;
            const uint2 ma = *(const uint2*)(dm0 + col);
            const uint2 mb = *(const uint2*)(dm1 + col);
            const float p0 = (ma.x || causal_masked(qr0, col))     ? 0.f : __expf(fs[j][0] * 0.125f);
            const float p1 = (ma.y || causal_masked(qr0, col + 1)) ? 0.f : __expf(fs[j][1] * 0.125f);
            const float p2 = (mb.x || causal_masked(qr1, col))     ? 0.f : __expf(fs[j][2] * 0.125f);
            const float p3 = (mb.y || causal_masked(qr1, col + 1)) ? 0.f : __expf(fs[j][3] * 0.125f);
            li0 += p0 + p1;
            li1 += p2 + p3;
            const bf16 h0 = __float2bfloat16_rn(p0), h1 = __float2bfloat16_rn(p1);
            const bf16 h2 = __float2bfloat16_rn(p2), h3 = __float2bfloat16_rn(p3);
            __nv_bfloat162 H01(h0, h1), H23(h2, h3);
            __nv_bfloat162 L01(__float2bfloat16_rn(p0 - __bfloat162float(h0)),
                               __float2bfloat16_rn(p1 - __bfloat162float(h1)));
            __nv_bfloat162 L23(__float2bfloat16_rn(p2 - __bfloat162float(h2)),
                               __float2bfloat16_rn(p3 - __bfloat162float(h3)));
            const int kt = j >> 1, hk = (j & 1) * 2;
            ph[kt][hk + 0] = *(uint32_t*)&H01;
            ph[kt][hk + 1] = *(uint32_t*)&H23;
            pl[kt][hk + 0] = *(uint32_t*)&L01;
            pl[kt][hk + 1] = *(uint32_t*)&L23;
        }

#pragma unroll
        for (int kt = 0; kt < 4; kt++) {
#pragma unroll
            for (int jp = 0; jp < 4; jp++) {
                uint32_t vh[4], vl[4];
                const uint32_t va = kb + 18432 + (kt * 16 + (lm & 1) * 8 + lr) * SBQB
                                  + jp * 32 + (lm >> 1) * 16;
                ldmx4t(vh, va);
                ldmx4t(vl, va + 9216);
                mma16816(fo[2*jp],   ph[kt], vh);
                mma16816(fo[2*jp],   ph[kt], vl);
                mma16816(fo[2*jp],   pl[kt], vh);
                mma16816(fo[2*jp+1], ph[kt], vh + 2);
                mma16816(fo[2*jp+1], ph[kt], vl + 2);
                mma16816(fo[2*jp+1], pl[kt], vh + 2);
            }
        }

        if (s + 1 < nt) {
            asm volatile("cp.async.wait_group 0;" ::: "memory");
            __syncthreads();
        }
    }

    li0 += __shfl_xor_sync(0xffffffffu, li0, 1);
    li0 += __shfl_xor_sync(0xffffffffu, li0, 2);
    li1 += __shfl_xor_sync(0xffffffffu, li1, 1);
    li1 += __shfl_xor_sync(0xffffffffu, li1, 2);

    bf16* yh0 = yh + ((size_t)b * T_ + qr0) * C_ + h * 64;
    bf16* yl0 = yl + ((size_t)b * T_ + qr0) * C_ + h * 64;
    bf16* yh1 = yh + ((size_t)b * T_ + qr1) * C_ + h * 64;
    bf16* yl1 = yl + ((size_t)b * T_ + qr1) * C_ + h * 64;
#pragma unroll
    for (int j = 0; j < 8; j++) {
        const int col = j * 8 + t2;
        const float v0 = fo[j][0] / li0, v1 = fo[j][1] / li0;
        const float v2 = fo[j][2] / li1, v3 = fo[j][3] / li1;
        const bf16 h0 = __float2bfloat16_rn(v0), h1 = __float2bfloat16_rn(v1);
        const bf16 h2 = __float2bfloat16_rn(v2), h3 = __float2bfloat16_rn(v3);
        *(__nv_bfloat162*)(yh0 + col) = __nv_bfloat162(h0, h1);
        *(__nv_bfloat162*)(yl0 + col) =
            __nv_bfloat162(__float2bfloat16_rn(v0 - __bfloat162float(h0)),
                           __float2bfloat16_rn(v1 - __bfloat162float(h1)));
        *(__nv_bfloat162*)(yh1 + col) = __nv_bfloat162(h2, h3);
        *(__nv_bfloat162*)(yl1 + col) =
            __nv_bfloat162(__float2bfloat16_rn(v2 - __bfloat162float(h2)),
                           __float2bfloat16_rn(v3 - __bfloat162float(h3)));
    }
}

// ---------------------------------------------------------------------------
extern "C" void kernel_launch(void* const* d_in, const int* in_sizes, int n_in,
                              void* d_out, int out_size)
{
    const float* x  = (const float*)d_in[0];
    const uint32_t* dmask = (const uint32_t*)d_in[1];
    const float* Wq = (const float*)d_in[3];
    const float* bq = (const float*)d_in[4];
    const float* Wk = (const float*)d_in[5];
    const float* bk = (const float*)d_in[6];
    const float* Wv = (const float*)d_in[7];
    const float* bv = (const float*)d_in[8];
    const float* Wo = (const float*)d_in[9];
    const float* bo = (const float*)d_in[10];

    bf16 *ah, *al, *wh, *wl, *yh, *yl;
    cudaGetSymbolAddress((void**)&ah, g_ah);
    cudaGetSymbolAddress((void**)&al, g_al);
    cudaGetSymbolAddress((void**)&wh, g_wh);
    cudaGetSymbolAddress((void**)&wl, g_wl);
    cudaGetSymbolAddress((void**)&yh, g_yh);
    cudaGetSymbolAddress((void**)&yl, g_yl);

    split_kernel<<<(MTOT * C_ / 4 + 255) / 256, 256>>>(x, ah, al, MTOT * C_ / 4);
    const int wn4 = C_ * C_ / 4;
    split4_kernel<<<dim3((wn4 + 255) / 256, 4), 256>>>(Wq, Wk, Wv, Wo, wh, wl, wn4);

    cudaFuncSetAttribute(gemm_mma<0>, cudaFuncAttributeMaxDynamicSharedMemorySize, GSMEM2);
    cudaFuncSetAttribute(gemm_mma<1>, cudaFuncAttributeMaxDynamicSharedMemorySize, GSMEM2);
    cudaFuncSetAttribute(attn_reg, cudaFuncAttributeMaxDynamicSharedMemorySize, ASMEM);

    gemm_mma<0><<<dim3(C_ / 128, MTOT / 128, 3), 128, GSMEM2>>>(
        ah, al, wh, wl, bq, bk, bv, nullptr);

    attn_reg<<<dim3(T_ / 128, H_, B_), 256, ASMEM>>>(dmask, yh, yl);

    gemm_mma<1><<<dim3(C_ / 128, MTOT / 128), 128, GSMEM2>>>(
        yh, yl, wh + 3 * C_ * C_, wl + 3 * C_ * C_, bo, nullptr, nullptr, (float*)d_out);
}

// round 10
// speedup vs baseline: 2.8542x; 1.3570x over previous
#include <cuda_runtime.h>
#include <cuda_bf16.h>
#include <math.h>
#include <stdint.h>

#define B_ 2
#define T_ 2048
#define C_ 1024
#define H_ 16
#define D_ 64
#define MTOT (B_*T_)          // 4096

typedef __nv_bfloat16 bf16;

// ---------------- scratch (__device__ globals; no allocs allowed) ----------
__device__ bf16 g_qh[B_*H_*T_*D_];
__device__ bf16 g_ql[B_*H_*T_*D_];
__device__ bf16 g_kh[B_*H_*T_*D_];
__device__ bf16 g_kl[B_*H_*T_*D_];
__device__ bf16 g_vh[B_*H_*T_*D_];
__device__ bf16 g_vl[B_*H_*T_*D_];
__device__ bf16 g_ah[MTOT*C_];
__device__ bf16 g_al[MTOT*C_];
__device__ bf16 g_wh[4*C_*C_];
__device__ bf16 g_wl[4*C_*C_];
__device__ bf16 g_yh[MTOT*C_];
__device__ bf16 g_yl[MTOT*C_];
__device__ uint32_t g_pm[B_*T_*(T_/32)];   // packed (dynamic|causal) mask, 1MB

// ---------------- helpers --------------------------------------------------
__device__ __forceinline__ uint32_t smem_u32(const void* p) {
    uint32_t a;
    asm("{ .reg .u64 t; cvta.to.shared.u64 t, %1; cvt.u32.u64 %0, t; }" : "=r"(a) : "l"(p));
    return a;
}
__device__ __forceinline__ void cp_async16(uint32_t dst, const void* src) {
    asm volatile("cp.async.cg.shared.global [%0], [%1], 16;" :: "r"(dst), "l"(src) : "memory");
}
__device__ __forceinline__ void ldmx4(uint32_t* r, uint32_t a) {
    asm volatile("ldmatrix.sync.aligned.m8n8.x4.shared.b16 {%0,%1,%2,%3}, [%4];"
                 : "=r"(r[0]), "=r"(r[1]), "=r"(r[2]), "=r"(r[3]) : "r"(a));
}
__device__ __forceinline__ void ldmx4t(uint32_t* r, uint32_t a) {
    asm volatile("ldmatrix.sync.aligned.m8n8.x4.trans.shared.b16 {%0,%1,%2,%3}, [%4];"
                 : "=r"(r[0]), "=r"(r[1]), "=r"(r[2]), "=r"(r[3]) : "r"(a));
}
__device__ __forceinline__ void mma16816(float* c, const uint32_t* a, const uint32_t* b) {
    asm volatile("mma.sync.aligned.m16n8k16.row.col.f32.bf16.bf16.f32 "
                 "{%0,%1,%2,%3}, {%4,%5,%6,%7}, {%8,%9}, {%0,%1,%2,%3};"
                 : "+f"(c[0]), "+f"(c[1]), "+f"(c[2]), "+f"(c[3])
                 : "r"(a[0]), "r"(a[1]), "r"(a[2]), "r"(a[3]), "r"(b[0]), "r"(b[1]));
}

// ---------------- analytic causal/step mask --------------------------------
__device__ __forceinline__ bool causal_masked(int q, int k) {
    const bool step = (q >> 5) == (k >> 5);
    const bool tri  = (k <= q) && ((q & 3) != 3) && ((k & 3) != 3);
    return !(step || tri);
}

// ---------------- split fp32 -> bf16 hi/lo ---------------------------------
__device__ __forceinline__ void split_body(const float* __restrict__ in,
                                           bf16* __restrict__ hi, bf16* __restrict__ lo, int i)
{
    float4 v = ((const float4*)in)[i];
    bf16 h0 = __float2bfloat16_rn(v.x);
    bf16 h1 = __float2bfloat16_rn(v.y);
    bf16 h2 = __float2bfloat16_rn(v.z);
    bf16 h3 = __float2bfloat16_rn(v.w);
    bf16 l0 = __float2bfloat16_rn(v.x - __bfloat162float(h0));
    bf16 l1 = __float2bfloat16_rn(v.y - __bfloat162float(h1));
    bf16 l2 = __float2bfloat16_rn(v.z - __bfloat162float(h2));
    bf16 l3 = __float2bfloat16_rn(v.w - __bfloat162float(h3));
    __nv_bfloat162* hp = (__nv_bfloat162*)hi;
    __nv_bfloat162* lp = (__nv_bfloat162*)lo;
    hp[2*i]   = __nv_bfloat162(h0, h1);
    hp[2*i+1] = __nv_bfloat162(h2, h3);
    lp[2*i]   = __nv_bfloat162(l0, l1);
    lp[2*i+1] = __nv_bfloat162(l2, l3);
}
__global__ void split_kernel(const float* __restrict__ in,
                             bf16* __restrict__ hi, bf16* __restrict__ lo, int n4)
{
    const int i = blockIdx.x * blockDim.x + threadIdx.x;
    if (i < n4) split_body(in, hi, lo, i);
}
__global__ void split4_kernel(const float* __restrict__ w0, const float* __restrict__ w1,
                              const float* __restrict__ w2, const float* __restrict__ w3,
                              bf16* __restrict__ hi, bf16* __restrict__ lo, int n4)
{
    const int z = blockIdx.y;
    const float* src = (z == 0) ? w0 : (z == 1) ? w1 : (z == 2) ? w2 : w3;
    const int i = blockIdx.x * blockDim.x + threadIdx.x;
    if (i < n4) split_body(src, hi + (size_t)z * C_ * C_, lo + (size_t)z * C_ * C_, i);
}

// ---------------- pack (dynamic | causal) mask into bits -------------------
__global__ void pack_mask(const uint32_t* __restrict__ dmask, uint32_t* __restrict__ pm)
{
    const int idx = blockIdx.x * 256 + threadIdx.x;     // b*T*64 + q*64 + w
    const int w = idx & 63;
    const int q = (idx >> 6) & (T_ - 1);
    const int b = idx >> 17;
    const uint32_t* src = dmask + ((size_t)b * T_ + q) * T_ + w * 32;
    const int kbase = w * 32;
    uint32_t bits = 0;
#pragma unroll
    for (int i = 0; i < 32; i += 4) {
        const uint4 v = *(const uint4*)(src + i);
        if (v.x || causal_masked(q, kbase + i + 0)) bits |= 1u << (i + 0);
        if (v.y || causal_masked(q, kbase + i + 1)) bits |= 1u << (i + 1);
        if (v.z || causal_masked(q, kbase + i + 2)) bits |= 1u << (i + 2);
        if (v.w || causal_masked(q, kbase + i + 3)) bits |= 1u << (i + 3);
    }
    pm[idx] = bits;
}

// ---------------- raw-mma bf16-split GEMM (unchanged) ----------------------
#define GARR 8192
#define GSTAGE 32768
#define GSMEM2 (3*GSTAGE)

template<int MODE>
__global__ __launch_bounds__(128, 2)
void gemm_mma(const bf16* __restrict__ Ah, const bf16* __restrict__ Al,
              const bf16* __restrict__ WhBase, const bf16* __restrict__ WlBase,
              const float* __restrict__ b0, const float* __restrict__ b1,
              const float* __restrict__ b2, float* __restrict__ out_f)
{
    extern __shared__ char dynsmem[];
    const uint32_t sb = smem_u32(dynsmem);

    const int z = (MODE == 0) ? (int)blockIdx.z : 0;
    const bf16* Bh = WhBase + (size_t)z * C_ * C_;
    const bf16* Bl = WlBase + (size_t)z * C_ * C_;
    const float* bias = (z == 0) ? b0 : (z == 1) ? b1 : b2;
    bf16* outh = (MODE == 0) ? ((z == 0) ? g_qh : (z == 1) ? g_kh : g_vh) : nullptr;
    bf16* outl = (MODE == 0) ? ((z == 0) ? g_ql : (z == 1) ? g_kl : g_vl) : nullptr;

    const int tid = threadIdx.x, wid = tid >> 5, lane = tid & 31;
    const int warp_m = wid >> 1, warp_n = wid & 1;
    const int g = lane >> 2, t2 = (lane & 3) * 2;
    const int lm = lane >> 3, lr = lane & 7;
    const int n0 = blockIdx.x * 128, m0 = blockIdx.y * 128;

    auto issue = [&](int s, int st) {
        const int c0 = s * 32;
#pragma unroll
        for (int i = 0; i < 16; i++) {
            const int idx = i * 128 + tid;
            const int arr = idx >> 9, rem = idx & 511;
            const int r = rem >> 2, c = rem & 3;
            const bf16* gp = (arr == 0) ? Ah : (arr == 1) ? Al : (arr == 2) ? Bh : Bl;
            const int row = ((arr < 2) ? m0 : n0) + r;
            cp_async16(sb + st * GSTAGE + arr * GARR + r * 64 + ((c ^ (r & 3)) * 16),
                       gp + (size_t)row * 1024 + c0 + c * 8);
        }
        asm volatile("cp.async.commit_group;" ::: "memory");
    };

    float fc[4][8][4];
#pragma unroll
    for (int im = 0; im < 4; im++)
#pragma unroll
        for (int j = 0; j < 8; j++)
#pragma unroll
            for (int e = 0; e < 4; e++) fc[im][j][e] = 0.f;

    issue(0, 0); issue(1, 1); issue(2, 2);

    for (int s = 0; s < 32; s++) {
        if (s < 30) { asm volatile("cp.async.wait_group 2;" ::: "memory"); }
        else        { asm volatile("cp.async.wait_group 0;" ::: "memory"); }
        __syncthreads();

        const uint32_t stb = sb + (s % 3) * GSTAGE;
#pragma unroll
        for (int kt = 0; kt < 2; kt++) {
            uint32_t bh4[4][4], bl4[4][4];
#pragma unroll
            for (int jp = 0; jp < 4; jp++) {
                const int row = warp_n * 64 + jp * 16 + (lm >> 1) * 8 + lr;
                const int c = kt * 2 + (lm & 1);
                const uint32_t a = stb + 2 * GARR + row * 64 + ((c ^ (row & 3)) * 16);
                ldmx4(bh4[jp], a);
                ldmx4(bl4[jp], a + GARR);
            }
#pragma unroll
            for (int im = 0; im < 4; im++) {
                const int row = warp_m * 64 + im * 16 + (lm & 1) * 8 + lr;
                const int c = kt * 2 + (lm >> 1);
                const uint32_t a = stb + row * 64 + ((c ^ (row & 3)) * 16);
                uint32_t ahf[4], alf[4];
                ldmx4(ahf, a);
                ldmx4(alf, a + GARR);
#pragma unroll
                for (int jp = 0; jp < 4; jp++) {
                    mma16816(fc[im][2*jp],   ahf, bh4[jp]);
                    mma16816(fc[im][2*jp],   ahf, bl4[jp]);
                    mma16816(fc[im][2*jp],   alf, bh4[jp]);
                    mma16816(fc[im][2*jp+1], ahf, bh4[jp] + 2);
                    mma16816(fc[im][2*jp+1], ahf, bl4[jp] + 2);
                    mma16816(fc[im][2*jp+1], alf, bh4[jp] + 2);
                }
            }
        }
        __syncthreads();
        if (s + 3 < 32) issue(s + 3, (s + 3) % 3);
    }

#pragma unroll
    for (int jp = 0; jp < 4; jp++)
#pragma unroll
        for (int n8 = 0; n8 < 2; n8++) {
            const int col = n0 + warp_n * 64 + jp * 16 + n8 * 8 + t2;
            const float bx = __ldg(&bias[col]), by = __ldg(&bias[col + 1]);
#pragma unroll
            for (int im = 0; im < 4; im++) {
                const float* cc = fc[im][2 * jp + n8];
                const int r0 = m0 + warp_m * 64 + im * 16 + g;
                const float v0 = cc[0] + bx, v1 = cc[1] + by;
                const float v2 = cc[2] + bx, v3 = cc[3] + by;
                if (MODE == 0) {
                    const int hh = col >> 6, dd = col & 63;
                    const int bb0 = r0 >> 11, tt0 = r0 & (T_ - 1);
                    const size_t o0 = (((size_t)bb0 * H_ + hh) * T_ + tt0) * D_ + dd;
                    const int r1 = r0 + 8;
                    const int bb1 = r1 >> 11, tt1 = r1 & (T_ - 1);
                    const size_t o1 = (((size_t)bb1 * H_ + hh) * T_ + tt1) * D_ + dd;
                    const bf16 h0 = __float2bfloat16_rn(v0), h1 = __float2bfloat16_rn(v1);
                    const bf16 h2 = __float2bfloat16_rn(v2), h3 = __float2bfloat16_rn(v3);
                    *(__nv_bfloat162*)(outh + o0) = __nv_bfloat162(h0, h1);
                    *(__nv_bfloat162*)(outl + o0) =
                        __nv_bfloat162(__float2bfloat16_rn(v0 - __bfloat162float(h0)),
                                       __float2bfloat16_rn(v1 - __bfloat162float(h1)));
                    *(__nv_bfloat162*)(outh + o1) = __nv_bfloat162(h2, h3);
                    *(__nv_bfloat162*)(outl + o1) =
                        __nv_bfloat162(__float2bfloat16_rn(v2 - __bfloat162float(h2)),
                                       __float2bfloat16_rn(v3 - __bfloat162float(h3)));
                } else {
                    *(float2*)(out_f + (size_t)r0 * C_ + col) = make_float2(v0, v1);
                    *(float2*)(out_f + (size_t)(r0 + 8) * C_ + col) = make_float2(v2, v3);
                }
            }
        }
}

// ---------------- register-resident flash attention, 2 CTA/SM --------------
// XOR-swizzled 128B rows (no pad). Q staged in [0,32KB) then consumed into
// registers; same region reused as KV ring buffer (3 x 32KB). Packed mask.
#define AARR 8192           // one KV array: 64 rows x 128B
#define AKVB 32768          // Kh,Kl,Vh,Vl
#define ASMEM3 (3*AKVB)     // 98304

__global__ __launch_bounds__(256, 2)
void attn_reg(const uint32_t* __restrict__ pmask,
              bf16* __restrict__ yh, bf16* __restrict__ yl)
{
    extern __shared__ char dyn[];
    const uint32_t sb = smem_u32(dyn);
    const int b = blockIdx.z, h = blockIdx.y;
    const int qi = (int)gridDim.x - 1 - (int)blockIdx.x;   // heavy first
    const int q0 = qi * 128;
    const int tid = threadIdx.x, wid = tid >> 5, lane = tid & 31;
    const int g = lane >> 2, t2 = (lane & 3) * 2;
    const int lm = lane >> 3, lr = lane & 7;
    const size_t headoff = ((size_t)b * H_ + h) * T_;

    // ---- stage Q (hi/lo) into [0, 32KB), swizzled ----
    {
        const bf16* qhg = g_qh + (headoff + q0) * D_;
        const bf16* qlg = g_ql + (headoff + q0) * D_;
#pragma unroll
        for (int i = 0; i < 8; i++) {
            const int c = tid + i * 256;
            const int arr = c >> 10;
            const int rem = c & 1023;
            const int r = rem >> 3, ch = rem & 7;
            const bf16* gp = arr ? qlg : qhg;
            cp_async16(sb + arr * 16384 + r * 128 + ((ch ^ (r & 7)) << 4),
                       gp + (size_t)r * D_ + ch * 8);
        }
        asm volatile("cp.async.commit_group;" ::: "memory");
        asm volatile("cp.async.wait_group 0;" ::: "memory");
        __syncthreads();
    }

    // ---- Q fragments into registers (once) ----
    uint32_t qfh[4][4], qfl[4][4];
#pragma unroll
    for (int kt = 0; kt < 4; kt++) {
        const int row = wid * 16 + (lm & 1) * 8 + lr;
        const int c = kt * 2 + (lm >> 1);
        const uint32_t a = sb + row * 128 + ((c ^ (row & 7)) << 4);
        ldmx4(qfh[kt], a);
        ldmx4(qfl[kt], a + 16384);
    }
    __syncthreads();   // Q smem consumed; region now free for KV ring

    auto issueKV = [&](int kt, int buf) {
        const int k0 = kt * 64;
#pragma unroll
        for (int i = 0; i < 8; i++) {
            const int c = tid + i * 256;
            const int arr = c >> 9;
            const int rem = c & 511;
            const int r = rem >> 3, ch = rem & 7;
            const bf16* gp = (arr == 0) ? g_kh : (arr == 1) ? g_kl : (arr == 2) ? g_vh : g_vl;
            cp_async16(sb + buf * AKVB + arr * AARR + r * 128 + ((ch ^ (r & 7)) << 4),
                       gp + (headoff + k0 + r) * D_ + ch * 8);
        }
        asm volatile("cp.async.commit_group;" ::: "memory");
    };

    float fo[8][4];
#pragma unroll
    for (int j = 0; j < 8; j++)
#pragma unroll
        for (int e = 0; e < 4; e++) fo[j][e] = 0.f;
    float li0 = 0.f, li1 = 0.f;

    const int qr0 = q0 + wid * 16 + g, qr1 = qr0 + 8;
    const uint32_t* pm0 = pmask + ((size_t)b * T_ + qr0) * (T_ / 32);
    const uint32_t* pm1 = pmask + ((size_t)b * T_ + qr1) * (T_ / 32);

    const int nt = 2 * qi + 2;
    issueKV(0, 0);
    if (nt > 1) issueKV(1, 1);
    if (nt > 2) issueKV(2, 2);

    for (int s = 0; s < nt; s++) {
        const int rem_t = nt - 1 - s;
        if (rem_t >= 2)      { asm volatile("cp.async.wait_group 2;" ::: "memory"); }
        else if (rem_t == 1) { asm volatile("cp.async.wait_group 1;" ::: "memory"); }
        else                 { asm volatile("cp.async.wait_group 0;" ::: "memory"); }
        __syncthreads();

        const uint32_t kb = sb + (s % 3) * AKVB;
        const int k0 = s * 64;
        const uint2 mw0 = *(const uint2*)(pm0 + (k0 >> 5));
        const uint2 mw1 = *(const uint2*)(pm1 + (k0 >> 5));

        // ---- S = Q K^T : 16x64 in registers ----
        float fs[8][4];
#pragma unroll
        for (int j = 0; j < 8; j++)
#pragma unroll
            for (int e = 0; e < 4; e++) fs[j][e] = 0.f;
#pragma unroll
        for (int kt = 0; kt < 4; kt++) {
#pragma unroll
            for (int jp = 0; jp < 4; jp++) {
                uint32_t kh[4], kl[4];
                const int row = jp * 16 + (lm >> 1) * 8 + lr;
                const int c = kt * 2 + (lm & 1);
                const uint32_t ka = kb + row * 128 + ((c ^ (row & 7)) << 4);
                ldmx4(kh, ka);
                ldmx4(kl, ka + AARR);
                mma16816(fs[2*jp],   qfh[kt], kh);
                mma16816(fs[2*jp],   qfh[kt], kl);
                mma16816(fs[2*jp],   qfl[kt], kh);
                mma16816(fs[2*jp+1], qfh[kt], kh + 2);
                mma16816(fs[2*jp+1], qfh[kt], kl + 2);
                mma16816(fs[2*jp+1], qfl[kt], kh + 2);
            }
        }

        // ---- mask (packed bits) + exp + bf16-split, in registers ----
        uint32_t ph[4][4], pl[4][4];
#pragma unroll
        for (int j = 0; j < 8; j++) {
            const uint32_t w0 = (j < 4) ? mw0.x : mw0.y;
            const uint32_t w1 = (j < 4) ? mw1.x : mw1.y;
            const int bit = (j * 8 + t2) & 31;
            const float p0 = ((w0 >> bit) & 1u)       ? 0.f : __expf(fs[j][0] * 0.125f);
            const float p1 = ((w0 >> (bit + 1)) & 1u) ? 0.f : __expf(fs[j][1] * 0.125f);
            const float p2 = ((w1 >> bit) & 1u)       ? 0.f : __expf(fs[j][2] * 0.125f);
            const float p3 = ((w1 >> (bit + 1)) & 1u) ? 0.f : __expf(fs[j][3] * 0.125f);
            li0 += p0 + p1;
            li1 += p2 + p3;
            const bf16 h0 = __float2bfloat16_rn(p0), h1 = __float2bfloat16_rn(p1);
            const bf16 h2 = __float2bfloat16_rn(p2), h3 = __float2bfloat16_rn(p3);
            __nv_bfloat162 H01(h0, h1), H23(h2, h3);
            __nv_bfloat162 L01(__float2bfloat16_rn(p0 - __bfloat162float(h0)),
                               __float2bfloat16_rn(p1 - __bfloat162float(h1)));
            __nv_bfloat162 L23(__float2bfloat16_rn(p2 - __bfloat162float(h2)),
                               __float2bfloat16_rn(p3 - __bfloat162float(h3)));
            const int kt = j >> 1, hk = (j & 1) * 2;
            ph[kt][hk + 0] = *(uint32_t*)&H01;
            ph[kt][hk + 1] = *(uint32_t*)&H23;
            pl[kt][hk + 0] = *(uint32_t*)&L01;
            pl[kt][hk + 1] = *(uint32_t*)&L23;
        }

        // ---- O += P V : persistent register accumulators ----
#pragma unroll
        for (int kt = 0; kt < 4; kt++) {
#pragma unroll
            for (int jp = 0; jp < 4; jp++) {
                uint32_t vh[4], vl[4];
                const int row = kt * 16 + (lm & 1) * 8 + lr;
                const int c = jp * 2 + (lm >> 1);
                const uint32_t va = kb + 2 * AARR + row * 128 + ((c ^ (row & 7)) << 4);
                ldmx4t(vh, va);
                ldmx4t(vl, va + AARR);
                mma16816(fo[2*jp],   ph[kt], vh);
                mma16816(fo[2*jp],   ph[kt], vl);
                mma16816(fo[2*jp],   pl[kt], vh);
                mma16816(fo[2*jp+1], ph[kt], vh + 2);
                mma16816(fo[2*jp+1], ph[kt], vl + 2);
                mma16816(fo[2*jp+1], pl[kt], vh + 2);
            }
        }

        __syncthreads();                       // all warps done with buf s%3
        if (s + 3 < nt) issueKV(s + 3, (s + 3) % 3);
    }

    // ---- epilogue: quad-reduce li, divide (0/0 -> NaN), write bf16 hi/lo ----
    li0 += __shfl_xor_sync(0xffffffffu, li0, 1);
    li0 += __shfl_xor_sync(0xffffffffu, li0, 2);
    li1 += __shfl_xor_sync(0xffffffffu, li1, 1);
    li1 += __shfl_xor_sync(0xffffffffu, li1, 2);

    bf16* yh0 = yh + ((size_t)b * T_ + qr0) * C_ + h * 64;
    bf16* yl0 = yl + ((size_t)b * T_ + qr0) * C_ + h * 64;
    bf16* yh1 = yh + ((size_t)b * T_ + qr1) * C_ + h * 64;
    bf16* yl1 = yl + ((size_t)b * T_ + qr1) * C_ + h * 64;
#pragma unroll
    for (int j = 0; j < 8; j++) {
        const int col = j * 8 + t2;
        const float v0 = fo[j][0] / li0, v1 = fo[j][1] / li0;
        const float v2 = fo[j][2] / li1, v3 = fo[j][3] / li1;
        const bf16 h0 = __float2bfloat16_rn(v0), h1 = __float2bfloat16_rn(v1);
        const bf16 h2 = __float2bfloat16_rn(v2), h3 = __float2bfloat16_rn(v3);
        *(__nv_bfloat162*)(yh0 + col) = __nv_bfloat162(h0, h1);
        *(__nv_bfloat162*)(yl0 + col) =
            __nv_bfloat162(__float2bfloat16_rn(v0 - __bfloat162float(h0)),
                           __float2bfloat16_rn(v1 - __bfloat162float(h1)));
        *(__nv_bfloat162*)(yh1 + col) = __nv_bfloat162(h2, h3);
        *(__nv_bfloat162*)(yl1 + col) =
            __nv_bfloat162(__float2bfloat16_rn(v2 - __bfloat162float(h2)),
                           __float2bfloat16_rn(v3 - __bfloat162float(h3)));
    }
}

// ---------------------------------------------------------------------------
extern "C" void kernel_launch(void* const* d_in, const int* in_sizes, int n_in,
                              void* d_out, int out_size)
{
    const float* x  = (const float*)d_in[0];
    const uint32_t* dmask = (const uint32_t*)d_in[1];
    const float* Wq = (const float*)d_in[3];
    const float* bq = (const float*)d_in[4];
    const float* Wk = (const float*)d_in[5];
    const float* bk = (const float*)d_in[6];
    const float* Wv = (const float*)d_in[7];
    const float* bv = (const float*)d_in[8];
    const float* Wo = (const float*)d_in[9];
    const float* bo = (const float*)d_in[10];

    bf16 *ah, *al, *wh, *wl, *yh, *yl;
    uint32_t* pm;
    cudaGetSymbolAddress((void**)&ah, g_ah);
    cudaGetSymbolAddress((void**)&al, g_al);
    cudaGetSymbolAddress((void**)&wh, g_wh);
    cudaGetSymbolAddress((void**)&wl, g_wl);
    cudaGetSymbolAddress((void**)&yh, g_yh);
    cudaGetSymbolAddress((void**)&yl, g_yl);
    cudaGetSymbolAddress((void**)&pm, g_pm);

    split_kernel<<<(MTOT * C_ / 4 + 255) / 256, 256>>>(x, ah, al, MTOT * C_ / 4);
    const int wn4 = C_ * C_ / 4;
    split4_kernel<<<dim3((wn4 + 255) / 256, 4), 256>>>(Wq, Wk, Wv, Wo, wh, wl, wn4);
    pack_mask<<<B_ * T_ * (T_ / 32) / 256, 256>>>(dmask, pm);

    cudaFuncSetAttribute(gemm_mma<0>, cudaFuncAttributeMaxDynamicSharedMemorySize, GSMEM2);
    cudaFuncSetAttribute(gemm_mma<1>, cudaFuncAttributeMaxDynamicSharedMemorySize, GSMEM2);
    cudaFuncSetAttribute(attn_reg, cudaFuncAttributeMaxDynamicSharedMemorySize, ASMEM3);

    gemm_mma<0><<<dim3(C_ / 128, MTOT / 128, 3), 128, GSMEM2>>>(
        ah, al, wh, wl, bq, bk, bv, nullptr);

    attn_reg<<<dim3(T_ / 128, H_, B_), 256, ASMEM3>>>(pm, yh, yl);

    gemm_mma<1><<<dim3(C_ / 128, MTOT / 128), 128, GSMEM2>>>(
        yh, yl, wh + 3 * C_ * C_, wl + 3 * C_ * C_, bo, nullptr, nullptr, (float*)d_out);
}

// round 11
// speedup vs baseline: 4.1095x; 1.4398x over previous
#include <cuda_runtime.h>
#include <cuda_fp16.h>
#include <math.h>
#include <stdint.h>

#define B_ 2
#define T_ 2048
#define C_ 1024
#define H_ 16
#define D_ 64
#define MTOT (B_*T_)          // 4096

typedef __half fp16;

// ---------------- scratch (__device__ globals; no allocs allowed) ----------
__device__ fp16 g_qh[B_*H_*T_*D_];
__device__ fp16 g_ql[B_*H_*T_*D_];
__device__ fp16 g_kh[B_*H_*T_*D_];    // K single fp16
__device__ fp16 g_vh[B_*H_*T_*D_];
__device__ fp16 g_vl[B_*H_*T_*D_];
__device__ fp16 g_ah[MTOT*C_];        // x split hi
__device__ fp16 g_al[MTOT*C_];        // x split lo
__device__ fp16 g_wh[4*C_*C_];        // W single fp16 (Wq,Wk,Wv,Wo)
__device__ fp16 g_yh[MTOT*C_];        // attn out split hi
__device__ fp16 g_yl[MTOT*C_];        // lo
__device__ uint32_t g_pm[B_*T_*(T_/32)];   // packed (dynamic|causal) mask

// ---------------- helpers --------------------------------------------------
__device__ __forceinline__ uint32_t smem_u32(const void* p) {
    uint32_t a;
    asm("{ .reg .u64 t; cvta.to.shared.u64 t, %1; cvt.u32.u64 %0, t; }" : "=r"(a) : "l"(p));
    return a;
}
__device__ __forceinline__ void cp_async16(uint32_t dst, const void* src) {
    asm volatile("cp.async.cg.shared.global [%0], [%1], 16;" :: "r"(dst), "l"(src) : "memory");
}
__device__ __forceinline__ void ldmx4(uint32_t* r, uint32_t a) {
    asm volatile("ldmatrix.sync.aligned.m8n8.x4.shared.b16 {%0,%1,%2,%3}, [%4];"
                 : "=r"(r[0]), "=r"(r[1]), "=r"(r[2]), "=r"(r[3]) : "r"(a));
}
__device__ __forceinline__ void ldmx4t(uint32_t* r, uint32_t a) {
    asm volatile("ldmatrix.sync.aligned.m8n8.x4.trans.shared.b16 {%0,%1,%2,%3}, [%4];"
                 : "=r"(r[0]), "=r"(r[1]), "=r"(r[2]), "=r"(r[3]) : "r"(a));
}
__device__ __forceinline__ void mma16816(float* c, const uint32_t* a, const uint32_t* b) {
    asm volatile("mma.sync.aligned.m16n8k16.row.col.f32.f16.f16.f32 "
                 "{%0,%1,%2,%3}, {%4,%5,%6,%7}, {%8,%9}, {%0,%1,%2,%3};"
                 : "+f"(c[0]), "+f"(c[1]), "+f"(c[2]), "+f"(c[3])
                 : "r"(a[0]), "r"(a[1]), "r"(a[2]), "r"(a[3]), "r"(b[0]), "r"(b[1]));
}

// ---------------- analytic causal/step mask --------------------------------
__device__ __forceinline__ bool causal_masked(int q, int k) {
    const bool step = (q >> 5) == (k >> 5);
    const bool tri  = (k <= q) && ((q & 3) != 3) && ((k & 3) != 3);
    return !(step || tri);
}

// ---------------- split fp32 -> fp16 hi/lo, round fp32 -> fp16 -------------
__global__ void split_kernel(const float* __restrict__ in,
                             fp16* __restrict__ hi, fp16* __restrict__ lo, int n4)
{
    const int i = blockIdx.x * blockDim.x + threadIdx.x;
    if (i >= n4) return;
    float4 v = ((const float4*)in)[i];
    fp16 h0 = __float2half_rn(v.x);
    fp16 h1 = __float2half_rn(v.y);
    fp16 h2 = __float2half_rn(v.z);
    fp16 h3 = __float2half_rn(v.w);
    fp16 l0 = __float2half_rn(v.x - __half2float(h0));
    fp16 l1 = __float2half_rn(v.y - __half2float(h1));
    fp16 l2 = __float2half_rn(v.z - __half2float(h2));
    fp16 l3 = __float2half_rn(v.w - __half2float(h3));
    __half2* hp = (__half2*)hi;
    __half2* lp = (__half2*)lo;
    hp[2*i]   = __halves2half2(h0, h1);
    hp[2*i+1] = __halves2half2(h2, h3);
    lp[2*i]   = __halves2half2(l0, l1);
    lp[2*i+1] = __halves2half2(l2, l3);
}
__global__ void round4_kernel(const float* __restrict__ w0, const float* __restrict__ w1,
                              const float* __restrict__ w2, const float* __restrict__ w3,
                              fp16* __restrict__ out, int n4)
{
    const int z = blockIdx.y;
    const float* src = (z == 0) ? w0 : (z == 1) ? w1 : (z == 2) ? w2 : w3;
    const int i = blockIdx.x * blockDim.x + threadIdx.x;
    if (i >= n4) return;
    float4 v = ((const float4*)src)[i];
    __half2* op = (__half2*)(out + (size_t)z * C_ * C_);
    op[2*i]   = __halves2half2(__float2half_rn(v.x), __float2half_rn(v.y));
    op[2*i+1] = __halves2half2(__float2half_rn(v.z), __float2half_rn(v.w));
}

// ---------------- pack (dynamic | causal) mask into bits -------------------
__global__ void pack_mask(const uint32_t* __restrict__ dmask, uint32_t* __restrict__ pm)
{
    const int idx = blockIdx.x * 256 + threadIdx.x;
    const int w = idx & 63;
    const int q = (idx >> 6) & (T_ - 1);
    const int b = idx >> 17;
    const uint32_t* src = dmask + ((size_t)b * T_ + q) * T_ + w * 32;
    const int kbase = w * 32;
    uint32_t bits = 0;
#pragma unroll
    for (int i = 0; i < 32; i += 4) {
        const uint4 v = *(const uint4*)(src + i);
        if (v.x || causal_masked(q, kbase + i + 0)) bits |= 1u << (i + 0);
        if (v.y || causal_masked(q, kbase + i + 1)) bits |= 1u << (i + 1);
        if (v.z || causal_masked(q, kbase + i + 2)) bits |= 1u << (i + 2);
        if (v.w || causal_masked(q, kbase + i + 3)) bits |= 1u << (i + 3);
    }
    pm[idx] = bits;
}

// ---------------- raw-mma fp16 2-product GEMM ------------------------------
// out[m,n] = sum_k A[m,k]*W[n,k] + bias[n];  A ~ Ah+Al (fp16), W single fp16.
// 128 threads, 4 warps of 64x64; K-slab 32; 3-stage swizzled smem pipeline.
#define GARR 8192            // one array: 128 rows x 64B
#define GSTAGE 24576         // Ah, Al, W
#define GSMEM2 (3*GSTAGE)    // 73728

template<int MODE>
__global__ __launch_bounds__(128, 2)
void gemm_mma(const fp16* __restrict__ Ah, const fp16* __restrict__ Al,
              const fp16* __restrict__ WBase,
              const float* __restrict__ b0, const float* __restrict__ b1,
              const float* __restrict__ b2, float* __restrict__ out_f)
{
    extern __shared__ char dynsmem[];
    const uint32_t sb = smem_u32(dynsmem);

    const int z = (MODE == 0) ? (int)blockIdx.z : 0;
    const fp16* W = WBase + (size_t)z * C_ * C_;
    const float* bias = (z == 0) ? b0 : (z == 1) ? b1 : b2;
    fp16* outh = (MODE == 0) ? ((z == 0) ? g_qh : (z == 1) ? g_kh : g_vh) : nullptr;
    fp16* outl = (MODE == 0) ? ((z == 0) ? g_ql : (z == 1) ? nullptr : g_vl) : nullptr;

    const int tid = threadIdx.x, wid = tid >> 5, lane = tid & 31;
    const int warp_m = wid >> 1, warp_n = wid & 1;
    const int g = lane >> 2, t2 = (lane & 3) * 2;
    const int lm = lane >> 3, lr = lane & 7;
    const int n0 = blockIdx.x * 128, m0 = blockIdx.y * 128;

    auto issue = [&](int s, int st) {
        const int c0 = s * 32;
#pragma unroll
        for (int i = 0; i < 12; i++) {
            const int idx = i * 128 + tid;          // 0..1535
            const int arr = idx >> 9, rem = idx & 511;
            const int r = rem >> 2, c = rem & 3;
            const fp16* gp = (arr == 0) ? Ah : (arr == 1) ? Al : W;
            const int row = ((arr < 2) ? m0 : n0) + r;
            cp_async16(sb + st * GSTAGE + arr * GARR + r * 64 + ((c ^ (r & 3)) * 16),
                       gp + (size_t)row * 1024 + c0 + c * 8);
        }
        asm volatile("cp.async.commit_group;" ::: "memory");
    };

    float fc[4][8][4];
#pragma unroll
    for (int im = 0; im < 4; im++)
#pragma unroll
        for (int j = 0; j < 8; j++)
#pragma unroll
            for (int e = 0; e < 4; e++) fc[im][j][e] = 0.f;

    issue(0, 0); issue(1, 1); issue(2, 2);

    for (int s = 0; s < 32; s++) {
        if (s < 30) { asm volatile("cp.async.wait_group 2;" ::: "memory"); }
        else        { asm volatile("cp.async.wait_group 0;" ::: "memory"); }
        __syncthreads();

        const uint32_t stb = sb + (s % 3) * GSTAGE;
#pragma unroll
        for (int kt = 0; kt < 2; kt++) {
            uint32_t bw[4][4];
#pragma unroll
            for (int jp = 0; jp < 4; jp++) {
                const int row = warp_n * 64 + jp * 16 + (lm >> 1) * 8 + lr;
                const int c = kt * 2 + (lm & 1);
                ldmx4(bw[jp], stb + 2 * GARR + row * 64 + ((c ^ (row & 3)) * 16));
            }
#pragma unroll
            for (int im = 0; im < 4; im++) {
                const int row = warp_m * 64 + im * 16 + (lm & 1) * 8 + lr;
                const int c = kt * 2 + (lm >> 1);
                const uint32_t a = stb + row * 64 + ((c ^ (row & 3)) * 16);
                uint32_t ahf[4], alf[4];
                ldmx4(ahf, a);
                ldmx4(alf, a + GARR);
#pragma unroll
                for (int jp = 0; jp < 4; jp++) {
                    mma16816(fc[im][2*jp],   ahf, bw[jp]);
                    mma16816(fc[im][2*jp],   alf, bw[jp]);
                    mma16816(fc[im][2*jp+1], ahf, bw[jp] + 2);
                    mma16816(fc[im][2*jp+1], alf, bw[jp] + 2);
                }
            }
        }
        __syncthreads();
        if (s + 3 < 32) issue(s + 3, (s + 3) % 3);
    }

    // ---- epilogue ----
#pragma unroll
    for (int jp = 0; jp < 4; jp++)
#pragma unroll
        for (int n8 = 0; n8 < 2; n8++) {
            const int col = n0 + warp_n * 64 + jp * 16 + n8 * 8 + t2;
            const float bx = __ldg(&bias[col]), by = __ldg(&bias[col + 1]);
#pragma unroll
            for (int im = 0; im < 4; im++) {
                const float* cc = fc[im][2 * jp + n8];
                const int r0 = m0 + warp_m * 64 + im * 16 + g;
                const float v0 = cc[0] + bx, v1 = cc[1] + by;
                const float v2 = cc[2] + bx, v3 = cc[3] + by;
                if (MODE == 0) {
                    const int hh = col >> 6, dd = col & 63;
                    const int bb0 = r0 >> 11, tt0 = r0 & (T_ - 1);
                    const size_t o0 = (((size_t)bb0 * H_ + hh) * T_ + tt0) * D_ + dd;
                    const int r1 = r0 + 8;
                    const int bb1 = r1 >> 11, tt1 = r1 & (T_ - 1);
                    const size_t o1 = (((size_t)bb1 * H_ + hh) * T_ + tt1) * D_ + dd;
                    const fp16 h0 = __float2half_rn(v0), h1 = __float2half_rn(v1);
                    const fp16 h2 = __float2half_rn(v2), h3 = __float2half_rn(v3);
                    *(__half2*)(outh + o0) = __halves2half2(h0, h1);
                    *(__half2*)(outh + o1) = __halves2half2(h2, h3);
                    if (outl) {
                        *(__half2*)(outl + o0) =
                            __halves2half2(__float2half_rn(v0 - __half2float(h0)),
                                           __float2half_rn(v1 - __half2float(h1)));
                        *(__half2*)(outl + o1) =
                            __halves2half2(__float2half_rn(v2 - __half2float(h2)),
                                           __float2half_rn(v3 - __half2float(h3)));
                    }
                } else {
                    *(float2*)(out_f + (size_t)r0 * C_ + col) = make_float2(v0, v1);
                    *(float2*)(out_f + (size_t)(r0 + 8) * C_ + col) = make_float2(v2, v3);
                }
            }
        }
}

// ---------------- register-resident flash attention, fp16 ------------------
// Q split (Qh,Ql) x K single; P single x V split (Vh,Vl).  2 products each.
#define AARR 8192           // one KV array: 64 rows x 128B
#define AKVB 24576          // Kh, Vh, Vl
#define ASMEM3 (3*AKVB)     // 73728

__global__ __launch_bounds__(256, 2)
void attn_reg(const uint32_t* __restrict__ pmask,
              fp16* __restrict__ yh, fp16* __restrict__ yl)
{
    extern __shared__ char dyn[];
    const uint32_t sb = smem_u32(dyn);
    const int b = blockIdx.z, h = blockIdx.y;
    const int qi = (int)gridDim.x - 1 - (int)blockIdx.x;   // heavy first
    const int q0 = qi * 128;
    const int tid = threadIdx.x, wid = tid >> 5, lane = tid & 31;
    const int g = lane >> 2, t2 = (lane & 3) * 2;
    const int lm = lane >> 3, lr = lane & 7;
    const size_t headoff = ((size_t)b * H_ + h) * T_;

    // ---- stage Q (hi/lo) into [0, 32KB), swizzled ----
    {
        const fp16* qhg = g_qh + (headoff + q0) * D_;
        const fp16* qlg = g_ql + (headoff + q0) * D_;
#pragma unroll
        for (int i = 0; i < 8; i++) {
            const int c = tid + i * 256;
            const int arr = c >> 10;
            const int rem = c & 1023;
            const int r = rem >> 3, ch = rem & 7;
            const fp16* gp = arr ? qlg : qhg;
            cp_async16(sb + arr * 16384 + r * 128 + ((ch ^ (r & 7)) << 4),
                       gp + (size_t)r * D_ + ch * 8);
        }
        asm volatile("cp.async.commit_group;" ::: "memory");
        asm volatile("cp.async.wait_group 0;" ::: "memory");
        __syncthreads();
    }

    // ---- Q fragments into registers (once) ----
    uint32_t qfh[4][4], qfl[4][4];
#pragma unroll
    for (int kt = 0; kt < 4; kt++) {
        const int row = wid * 16 + (lm & 1) * 8 + lr;
        const int c = kt * 2 + (lm >> 1);
        const uint32_t a = sb + row * 128 + ((c ^ (row & 7)) << 4);
        ldmx4(qfh[kt], a);
        ldmx4(qfl[kt], a + 16384);
    }
    __syncthreads();   // Q smem consumed; region reused as KV ring

    auto issueKV = [&](int kt, int buf) {
        const int k0 = kt * 64;
#pragma unroll
        for (int i = 0; i < 6; i++) {
            const int c = tid + i * 256;            // 0..1535
            const int arr = c >> 9;
            const int rem = c & 511;
            const int r = rem >> 3, ch = rem & 7;
            const fp16* gp = (arr == 0) ? g_kh : (arr == 1) ? g_vh : g_vl;
            cp_async16(sb + buf * AKVB + arr * AARR + r * 128 + ((ch ^ (r & 7)) << 4),
                       gp + (headoff + k0 + r) * D_ + ch * 8);
        }
        asm volatile("cp.async.commit_group;" ::: "memory");
    };

    float fo[8][4];
#pragma unroll
    for (int j = 0; j < 8; j++)
#pragma unroll
        for (int e = 0; e < 4; e++) fo[j][e] = 0.f;
    float li0 = 0.f, li1 = 0.f;

    const int qr0 = q0 + wid * 16 + g, qr1 = qr0 + 8;
    const uint32_t* pm0 = pmask + ((size_t)b * T_ + qr0) * (T_ / 32);
    const uint32_t* pm1 = pmask + ((size_t)b * T_ + qr1) * (T_ / 32);

    const int nt = 2 * qi + 2;
    issueKV(0, 0);
    if (nt > 1) issueKV(1, 1);
    if (nt > 2) issueKV(2, 2);

    for (int s = 0; s < nt; s++) {
        const int rem_t = nt - 1 - s;
        if (rem_t >= 2)      { asm volatile("cp.async.wait_group 2;" ::: "memory"); }
        else if (rem_t == 1) { asm volatile("cp.async.wait_group 1;" ::: "memory"); }
        else                 { asm volatile("cp.async.wait_group 0;" ::: "memory"); }
        __syncthreads();

        const uint32_t kb = sb + (s % 3) * AKVB;
        const int k0 = s * 64;
        const uint2 mw0 = *(const uint2*)(pm0 + (k0 >> 5));
        const uint2 mw1 = *(const uint2*)(pm1 + (k0 >> 5));

        // ---- S = Q K^T : 16x64 in registers (2 products) ----
        float fs[8][4];
#pragma unroll
        for (int j = 0; j < 8; j++)
#pragma unroll
            for (int e = 0; e < 4; e++) fs[j][e] = 0.f;
#pragma unroll
        for (int kt = 0; kt < 4; kt++) {
#pragma unroll
            for (int jp = 0; jp < 4; jp++) {
                uint32_t kh[4];
                const int row = jp * 16 + (lm >> 1) * 8 + lr;
                const int c = kt * 2 + (lm & 1);
                ldmx4(kh, kb + row * 128 + ((c ^ (row & 7)) << 4));
                mma16816(fs[2*jp],   qfh[kt], kh);
                mma16816(fs[2*jp],   qfl[kt], kh);
                mma16816(fs[2*jp+1], qfh[kt], kh + 2);
                mma16816(fs[2*jp+1], qfl[kt], kh + 2);
            }
        }

        // ---- mask (packed bits) + exp -> single fp16 P, in registers ----
        uint32_t ph[4][4];
#pragma unroll
        for (int j = 0; j < 8; j++) {
            const uint32_t w0 = (j < 4) ? mw0.x : mw0.y;
            const uint32_t w1 = (j < 4) ? mw1.x : mw1.y;
            const int bit = (j * 8 + t2) & 31;
            const float p0 = ((w0 >> bit) & 1u)       ? 0.f : __expf(fs[j][0] * 0.125f);
            const float p1 = ((w0 >> (bit + 1)) & 1u) ? 0.f : __expf(fs[j][1] * 0.125f);
            const float p2 = ((w1 >> bit) & 1u)       ? 0.f : __expf(fs[j][2] * 0.125f);
            const float p3 = ((w1 >> (bit + 1)) & 1u) ? 0.f : __expf(fs[j][3] * 0.125f);
            li0 += p0 + p1;
            li1 += p2 + p3;
            __half2 H01 = __halves2half2(__float2half_rn(p0), __float2half_rn(p1));
            __half2 H23 = __halves2half2(__float2half_rn(p2), __float2half_rn(p3));
            const int kt = j >> 1, hk = (j & 1) * 2;
            ph[kt][hk + 0] = *(uint32_t*)&H01;
            ph[kt][hk + 1] = *(uint32_t*)&H23;
        }

        // ---- O += P V (2 products) ----
#pragma unroll
        for (int kt = 0; kt < 4; kt++) {
#pragma unroll
            for (int jp = 0; jp < 4; jp++) {
                uint32_t vh[4], vl[4];
                const int row = kt * 16 + (lm & 1) * 8 + lr;
                const int c = jp * 2 + (lm >> 1);
                const uint32_t va = kb + AARR + row * 128 + ((c ^ (row & 7)) << 4);
                ldmx4t(vh, va);
                ldmx4t(vl, va + AARR);
                mma16816(fo[2*jp],   ph[kt], vh);
                mma16816(fo[2*jp],   ph[kt], vl);
                mma16816(fo[2*jp+1], ph[kt], vh + 2);
                mma16816(fo[2*jp+1], ph[kt], vl + 2);
            }
        }

        __syncthreads();                       // all warps done with buf s%3
        if (s + 3 < nt) issueKV(s + 3, (s + 3) % 3);
    }

    // ---- epilogue: quad-reduce li, divide (0/0 -> NaN), write fp16 hi/lo ----
    li0 += __shfl_xor_sync(0xffffffffu, li0, 1);
    li0 += __shfl_xor_sync(0xffffffffu, li0, 2);
    li1 += __shfl_xor_sync(0xffffffffu, li1, 1);
    li1 += __shfl_xor_sync(0xffffffffu, li1, 2);

    fp16* yh0 = yh + ((size_t)b * T_ + qr0) * C_ + h * 64;
    fp16* yl0 = yl + ((size_t)b * T_ + qr0) * C_ + h * 64;
    fp16* yh1 = yh + ((size_t)b * T_ + qr1) * C_ + h * 64;
    fp16* yl1 = yl + ((size_t)b * T_ + qr1) * C_ + h * 64;
#pragma unroll
    for (int j = 0; j < 8; j++) {
        const int col = j * 8 + t2;
        const float v0 = fo[j][0] / li0, v1 = fo[j][1] / li0;
        const float v2 = fo[j][2] / li1, v3 = fo[j][3] / li1;
        const fp16 h0 = __float2half_rn(v0), h1 = __float2half_rn(v1);
        const fp16 h2 = __float2half_rn(v2), h3 = __float2half_rn(v3);
        *(__half2*)(yh0 + col) = __halves2half2(h0, h1);
        *(__half2*)(yl0 + col) =
            __halves2half2(__float2half_rn(v0 - __half2float(h0)),
                           __float2half_rn(v1 - __half2float(h1)));
        *(__half2*)(yh1 + col) = __halves2half2(h2, h3);
        *(__half2*)(yl1 + col) =
            __halves2half2(__float2half_rn(v2 - __half2float(h2)),
                           __float2half_rn(v3 - __half2float(h3)));
    }
}

// ---------------------------------------------------------------------------
extern "C" void kernel_launch(void* const* d_in, const int* in_sizes, int n_in,
                              void* d_out, int out_size)
{
    const float* x  = (const float*)d_in[0];
    const uint32_t* dmask = (const uint32_t*)d_in[1];
    const float* Wq = (const float*)d_in[3];
    const float* bq = (const float*)d_in[4];
    const float* Wk = (const float*)d_in[5];
    const float* bk = (const float*)d_in[6];
    const float* Wv = (const float*)d_in[7];
    const float* bv = (const float*)d_in[8];
    const float* Wo = (const float*)d_in[9];
    const float* bo = (const float*)d_in[10];

    fp16 *ah, *al, *wh, *yh, *yl;
    uint32_t* pm;
    cudaGetSymbolAddress((void**)&ah, g_ah);
    cudaGetSymbolAddress((void**)&al, g_al);
    cudaGetSymbolAddress((void**)&wh, g_wh);
    cudaGetSymbolAddress((void**)&yh, g_yh);
    cudaGetSymbolAddress((void**)&yl, g_yl);
    cudaGetSymbolAddress((void**)&pm, g_pm);

    split_kernel<<<(MTOT * C_ / 4 + 255) / 256, 256>>>(x, ah, al, MTOT * C_ / 4);
    const int wn4 = C_ * C_ / 4;
    round4_kernel<<<dim3((wn4 + 255) / 256, 4), 256>>>(Wq, Wk, Wv, Wo, wh, wn4);
    pack_mask<<<B_ * T_ * (T_ / 32) / 256, 256>>>(dmask, pm);

    cudaFuncSetAttribute(gemm_mma<0>, cudaFuncAttributeMaxDynamicSharedMemorySize, GSMEM2);
    cudaFuncSetAttribute(gemm_mma<1>, cudaFuncAttributeMaxDynamicSharedMemorySize, GSMEM2);
    cudaFuncSetAttribute(attn_reg, cudaFuncAttributeMaxDynamicSharedMemorySize, ASMEM3);

    gemm_mma<0><<<dim3(C_ / 128, MTOT / 128, 3), 128, GSMEM2>>>(
        ah, al, wh, bq, bk, bv, nullptr);

    attn_reg<<<dim3(T_ / 128, H_, B_), 256, ASMEM3>>>(pm, yh, yl);

    gemm_mma<1><<<dim3(C_ / 128, MTOT / 128), 128, GSMEM2>>>(
        yh, yl, wh + 3 * C_ * C_, bo, nullptr, nullptr, (float*)d_out);
}